// round 11
// baseline (speedup 1.0000x reference)
#include <cuda_runtime.h>
#include <cuda_bf16.h>
#include <cstdint>

#define Nn   50000
#define Ee   800000
#define HID  128
#define OUTC 64
#define NG   64
#define TEMP_INV (1.0f/101.0f)

// ---------------- scratch (all zero at load; k_final tail restores zeros) ----------------
static __device__ int    g_deg[Nn];
static __device__ float  g_dinv[Nn];
static __device__ int    g_rowptr[Nn + 1];
static __device__ int    g_cursor[Nn];
static __device__ __align__(8) int2 g_edge[Ee];     // (src row byte-offset, dinv[src] bits)
static __device__ float  g_gate0[Nn * 3];
static __device__ float  g_gate1[Nn * 3];
static __device__ float  g_bufA[Nn * HID];          // agg output (fp32)
static __device__ float  g_bufB[Nn * HID];          // layer-0 output (fp32)
static __device__ float  g_sums[NG * HID];
static __device__ float  g_cnt[NG];
static __device__ int    g_scanFlag[128];
static __device__ int    g_scanAgg[128];
// bf16 split transposed weights: [L][e][n][k], hi and lo
static __device__ __align__(16) __nv_bfloat16 g_Wh[2 * 3 * 128 * 128];
static __device__ __align__(16) __nv_bfloat16 g_Wl[2 * 3 * 128 * 128];

__device__ __forceinline__ uint32_t smem_u32(const void* p) {
    uint32_t a;
    asm("{ .reg .u64 t; cvta.to.shared.u64 t, %1; cvt.u32.u64 %0, t; }" : "=r"(a) : "l"(p));
    return a;
}

// ---------------- fused init: weight split + gates + degree hist ----------------
__global__ void k_init(const float* __restrict__ W0, const float* __restrict__ W1,
                       const float* __restrict__ top,
                       const float* __restrict__ Wg0, const float* __restrict__ Wg1,
                       const int* __restrict__ ei) {
    int i = blockIdx.x * blockDim.x + threadIdx.x;
    if (i < 2 * 3 * 16384) {
        int L = i / 49152, rem = i % 49152;
        int e = rem / 16384, nk = rem % 16384;
        int n = nk >> 7, k = nk & 127;
        const float* W = L ? W1 : W0;
        float w = W[e * 16384 + k * 128 + n];
        __nv_bfloat16 hi = __float2bfloat16_rn(w);
        g_Wh[i] = hi;
        g_Wl[i] = __float2bfloat16_rn(w - __bfloat162float(hi));
    }
    if (i < Ee) atomicAdd(&g_deg[ei[Ee + i]], 1);   // g_deg zeroed by previous run's tail
    if (i < Nn) {
        float t0 = top[i*4+0], t1 = top[i*4+1], t2 = top[i*4+2], t3 = top[i*4+3];
        #pragma unroll
        for (int L = 0; L < 2; L++) {
            const float* Wg = L ? Wg1 : Wg0;
            float* gate = L ? g_gate1 : g_gate0;
            float l[3];
            #pragma unroll
            for (int e = 0; e < 3; e++)
                l[e] = (t0*Wg[e*4+0] + t1*Wg[e*4+1] + t2*Wg[e*4+2] + t3*Wg[e*4+3]) * TEMP_INV;
            float mx = fmaxf(l[0], fmaxf(l[1], l[2]));
            float e0 = expf(l[0]-mx), e1 = expf(l[1]-mx), e2 = expf(l[2]-mx);
            float inv = 1.0f / (e0 + e1 + e2);
            gate[i*3+0] = e0*inv; gate[i*3+1] = e1*inv; gate[i*3+2] = e2*inv;
        }
    }
}

// ---------------- single-kernel scan (decoupled lookback) + dinv ----------------
__global__ void __launch_bounds__(512) k_scan() {
    int b = blockIdx.x, t = threadIdx.x;
    int i = b * 512 + t;
    int v = (i < Nn) ? g_deg[i] : 0;
    int lane = t & 31, w = t >> 5;
    int x = v;
    #pragma unroll
    for (int d = 1; d < 32; d <<= 1) {
        int y = __shfl_up_sync(0xFFFFFFFFu, x, d);
        if (lane >= d) x += y;
    }
    __shared__ int wsum[16];
    __shared__ int pref;
    if (lane == 31) wsum[w] = x;
    __syncthreads();
    if (w == 0) {
        int s = (lane < 16) ? wsum[lane] : 0;
        #pragma unroll
        for (int d = 1; d < 16; d <<= 1) {
            int y = __shfl_up_sync(0xFFFFFFFFu, s, d);
            if (lane >= d) s += y;
        }
        if (lane < 16) wsum[lane] = s;
        if (lane == 15) {
            atomicExch(&g_scanAgg[b], s);
            __threadfence();
            atomicExch(&g_scanFlag[b], 1);
        }
    }
    __syncthreads();
    int incl = x + (w ? wsum[w - 1] : 0);
    if (w == 0) {
        int sum = 0;
        for (int base = b - 1; base >= 0; base -= 32) {
            int j = base - lane;
            int a = 0;
            if (j >= 0) {
                while (atomicAdd(&g_scanFlag[j], 0) == 0) { }
                a = atomicAdd(&g_scanAgg[j], 0);
            }
            #pragma unroll
            for (int d = 16; d; d >>= 1) a += __shfl_down_sync(0xFFFFFFFFu, a, d);
            sum += __shfl_sync(0xFFFFFFFFu, a, 0);
        }
        if (lane == 0) pref = sum;
    }
    __syncthreads();
    if (i < Nn) {
        g_rowptr[i + 1] = incl + pref;
        g_dinv[i] = rsqrtf((float)(v + 1));
    }
    if (i == 0) g_rowptr[0] = 0;
}

__global__ void k_fill(const int* __restrict__ ei) {
    int i = blockIdx.x * blockDim.x + threadIdx.x;
    if (i >= Ee) return;
    int s = ei[i], d = ei[Ee + i];
    int p = g_rowptr[d] + atomicAdd(&g_cursor[d], 1);
    g_edge[p] = make_int2(s * 512, __float_as_int(g_dinv[s]));   // byte offset of src row
}

// ---------------- CSR aggregation, fp32 gather, 2 nodes per warp ----------------
__global__ void __launch_bounds__(256) k_agg(const float* __restrict__ hsrc) {
    int gw = (blockIdx.x * 256 + threadIdx.x) >> 5;   // warp id, < 25000
    int lane = threadIdx.x & 31;
    int half = lane >> 4, l16 = lane & 15;
    int node = gw * 2 + half;                          // < 50000 always
    float dd = g_dinv[node];
    const char* base = (const char*)hsrc + l16 * 32;   // this lane's 32B slice

    float acc[8];
    {
        const float4* p = (const float4*)(base + node * 512);
        float4 v0 = p[0], v1 = p[1];
        float s2 = dd * dd;
        acc[0]=v0.x*s2; acc[1]=v0.y*s2; acc[2]=v0.z*s2; acc[3]=v0.w*s2;
        acc[4]=v1.x*s2; acc[5]=v1.y*s2; acc[6]=v1.z*s2; acc[7]=v1.w*s2;
    }
    int j0 = g_rowptr[node], j1 = g_rowptr[node + 1];
    #pragma unroll 4
    for (int j = j0; j < j1; j++) {
        int2 ed = __ldg(&g_edge[j]);
        float wt = dd * __int_as_float(ed.y);
        const float4* p = (const float4*)(base + ed.x);
        float4 u0 = __ldg(p), u1 = __ldg(p + 1);
        acc[0]+=wt*u0.x; acc[1]+=wt*u0.y; acc[2]+=wt*u0.z; acc[3]+=wt*u0.w;
        acc[4]+=wt*u1.x; acc[5]+=wt*u1.y; acc[6]+=wt*u1.z; acc[7]+=wt*u1.w;
    }
    float4* o = (float4*)&g_bufA[node * 128 + l16 * 8];
    o[0] = make_float4(acc[0], acc[1], acc[2], acc[3]);
    o[1] = make_float4(acc[4], acc[5], acc[6], acc[7]);
}

// ---------------- mma.sync bf16-split fused MoE GEMM (cp.async pipelined) ----------------
#define SMA_HI  0
#define SMA_LO  32768
#define SMB0    65536
#define SMB1    131072
#define SM_BIAS 196608
#define SM_GATE (196608 + 1536)
#define SM_BAT  (196608 + 3072)
#define SMEM_MM (196608 + 3072 + 512)
#define SM_STG  SMB0

#define AOFF(row, k) ((row) * 256 + (((((k) >> 3) ^ ((row) & 7))) << 4) + (((k) & 7) << 1))

__device__ __forceinline__ void mma_bf16(float* c, const uint32_t* a, const uint32_t* b) {
    asm volatile("mma.sync.aligned.m16n8k16.row.col.f32.bf16.bf16.f32 "
        "{%0,%1,%2,%3}, {%4,%5,%6,%7}, {%8,%9}, {%0,%1,%2,%3};"
        : "+f"(c[0]), "+f"(c[1]), "+f"(c[2]), "+f"(c[3])
        : "r"(a[0]), "r"(a[1]), "r"(a[2]), "r"(a[3]), "r"(b[0]), "r"(b[1]));
}

__device__ __forceinline__ void cp16(uint32_t dst, const void* src) {
    asm volatile("cp.async.cg.shared.global [%0], [%1], 16;" :: "r"(dst), "l"(src));
}

__device__ __forceinline__ void issueB(uint32_t smb, int stagebase,
                                       int layer, int e, int tid) {
    const uint4* bh = (const uint4*)(g_Wh + (layer * 3 + e) * 16384);
    const uint4* bl = (const uint4*)(g_Wl + (layer * 3 + e) * 16384);
    #pragma unroll
    for (int it = 0; it < 4; it++) {
        int idx = it * 512 + tid;
        int n = idx >> 4, kc = idx & 15;
        int off = n * 256 + ((kc ^ (n & 7)) << 4);
        cp16(smb + stagebase + off,         bh + idx);
        cp16(smb + stagebase + 32768 + off, bl + idx);
    }
    asm volatile("cp.async.commit_group;");
}

__global__ void __launch_bounds__(512) k_gemm_mma(const float* __restrict__ bias3,
                                                  const int* __restrict__ batch,
                                                  int layer) {
    extern __shared__ __align__(16) char smc[];
    const uint32_t smb = smem_u32(smc);
    const int tid = threadIdx.x;
    const int baseM = blockIdx.x * 128;
    const float* gate = layer ? g_gate1 : g_gate0;
    float* bias_s = (float*)(smc + SM_BIAS);
    float* gate_s = (float*)(smc + SM_GATE);
    int*   bat_s  = (int*)(smc + SM_BAT);

    issueB(smb, SMB0, layer, 0, tid);

    if (tid < 384) {
        bias_s[tid] = bias3[tid];
        int gi = baseM * 3 + tid;
        gate_s[tid] = (gi < Nn * 3) ? gate[gi] : 0.f;
    }
    if (layer && tid >= 384 && tid < 512) {
        int r = tid - 384;
        int nn = baseM + r;
        bat_s[r] = (nn < Nn) ? batch[nn] : -1;
    }

    // ---- build A tile (bf16 hi/lo, swizzled) from fp32 bufA ----
    #pragma unroll
    for (int it = 0; it < 4; it++) {
        int idx = it * 512 + tid;
        int row = idx >> 4, kc = idx & 15;
        int grow = baseM + row;
        float4 v0 = make_float4(0.f,0.f,0.f,0.f), v1 = v0;
        if (grow < Nn) {
            const float4* p = (const float4*)(g_bufA + grow * 128 + kc * 8);
            v0 = p[0]; v1 = p[1];
        }
        float f[8] = {v0.x, v0.y, v0.z, v0.w, v1.x, v1.y, v1.z, v1.w};
        __nv_bfloat16 h[8], l[8];
        #pragma unroll
        for (int j = 0; j < 8; j++) {
            h[j] = __float2bfloat16_rn(f[j]);
            l[j] = __float2bfloat16_rn(f[j] - __bfloat162float(h[j]));
        }
        int off = row * 256 + ((kc ^ (row & 7)) << 4);
        *(uint4*)(smc + SMA_HI + off) = *(uint4*)h;
        *(uint4*)(smc + SMA_LO + off) = *(uint4*)l;
    }

    const int lane = tid & 31, wid = tid >> 5;
    const int warpM = wid >> 2, warpN = wid & 3;
    const int g = lane >> 2, t4 = lane & 3;

    float out[2][4][4];
    #pragma unroll
    for (int mt = 0; mt < 2; mt++)
        #pragma unroll
        for (int nt = 0; nt < 4; nt++)
            #pragma unroll
            for (int j = 0; j < 4; j++) out[mt][nt][j] = 0.f;

    #pragma unroll 1
    for (int e = 0; e < 3; e++) {
        __syncthreads();
        if (e < 2) issueB(smb, (e & 1) ? SMB0 : SMB1, layer, e + 1, tid);
        if (e < 2) { asm volatile("cp.async.wait_group 1;"); }
        else       { asm volatile("cp.async.wait_group 0;"); }
        __syncthreads();

        const int sb  = (e & 1) ? SMB1 : SMB0;
        const int sbl = sb + 32768;

        float acc[2][4][4];
        #pragma unroll
        for (int mt = 0; mt < 2; mt++)
            #pragma unroll
            for (int nt = 0; nt < 4; nt++)
                #pragma unroll
                for (int j = 0; j < 4; j++) acc[mt][nt][j] = 0.f;

        #pragma unroll
        for (int ks = 0; ks < 8; ks++) {
            const int c0 = ks * 16 + t4 * 2;
            uint32_t afh[2][4], afl[2][4], bfh[4][2], bfl[4][2];
            #pragma unroll
            for (int mt = 0; mt < 2; mt++) {
                int r0 = warpM * 32 + mt * 16 + g;
                afh[mt][0] = *(const uint32_t*)(smc + SMA_HI + AOFF(r0,     c0));
                afh[mt][1] = *(const uint32_t*)(smc + SMA_HI + AOFF(r0 + 8, c0));
                afh[mt][2] = *(const uint32_t*)(smc + SMA_HI + AOFF(r0,     c0 + 8));
                afh[mt][3] = *(const uint32_t*)(smc + SMA_HI + AOFF(r0 + 8, c0 + 8));
                afl[mt][0] = *(const uint32_t*)(smc + SMA_LO + AOFF(r0,     c0));
                afl[mt][1] = *(const uint32_t*)(smc + SMA_LO + AOFF(r0 + 8, c0));
                afl[mt][2] = *(const uint32_t*)(smc + SMA_LO + AOFF(r0,     c0 + 8));
                afl[mt][3] = *(const uint32_t*)(smc + SMA_LO + AOFF(r0 + 8, c0 + 8));
            }
            #pragma unroll
            for (int nt = 0; nt < 4; nt++) {
                int n0 = warpN * 32 + nt * 8 + g;
                bfh[nt][0] = *(const uint32_t*)(smc + sb  + AOFF(n0, c0));
                bfh[nt][1] = *(const uint32_t*)(smc + sb  + AOFF(n0, c0 + 8));
                bfl[nt][0] = *(const uint32_t*)(smc + sbl + AOFF(n0, c0));
                bfl[nt][1] = *(const uint32_t*)(smc + sbl + AOFF(n0, c0 + 8));
            }
            #pragma unroll
            for (int mt = 0; mt < 2; mt++)
                #pragma unroll
                for (int nt = 0; nt < 4; nt++) {
                    mma_bf16(acc[mt][nt], afh[mt], bfh[nt]);
                    mma_bf16(acc[mt][nt], afl[mt], bfh[nt]);
                    mma_bf16(acc[mt][nt], afh[mt], bfl[nt]);
                }
        }

        #pragma unroll
        for (int mt = 0; mt < 2; mt++) {
            int rloc = warpM * 32 + mt * 16 + g;
            float g0 = gate_s[rloc * 3 + e];
            float g1 = gate_s[(rloc + 8) * 3 + e];
            #pragma unroll
            for (int nt = 0; nt < 4; nt++) {
                int col = warpN * 32 + nt * 8 + t4 * 2;
                float bb0 = bias_s[e * 128 + col], bb1 = bias_s[e * 128 + col + 1];
                out[mt][nt][0] += g0 * fmaxf(acc[mt][nt][0] + bb0, 0.f);
                out[mt][nt][1] += g0 * fmaxf(acc[mt][nt][1] + bb1, 0.f);
                out[mt][nt][2] += g1 * fmaxf(acc[mt][nt][2] + bb0, 0.f);
                out[mt][nt][3] += g1 * fmaxf(acc[mt][nt][3] + bb1, 0.f);
            }
        }
    }

    if (!layer) {
        // ---- layer 0: write h (fp32) for the next gather ----
        #pragma unroll
        for (int mt = 0; mt < 2; mt++) {
            int r0 = baseM + warpM * 32 + mt * 16 + g;
            #pragma unroll
            for (int nt = 0; nt < 4; nt++) {
                int col = warpN * 32 + nt * 8 + t4 * 2;
                if (r0 < Nn)
                    *(float2*)(g_bufB + r0 * 128 + col) = make_float2(out[mt][nt][0], out[mt][nt][1]);
                if (r0 + 8 < Nn)
                    *(float2*)(g_bufB + (r0 + 8) * 128 + col) = make_float2(out[mt][nt][2], out[mt][nt][3]);
            }
        }
    } else {
        // ---- layer 1: fused pooling via smem staging + segment scan ----
        __syncthreads();
        float* stg = (float*)(smc + SM_STG);
        #pragma unroll
        for (int mt = 0; mt < 2; mt++) {
            int rloc = warpM * 32 + mt * 16 + g;
            #pragma unroll
            for (int nt = 0; nt < 4; nt++) {
                int col = warpN * 32 + nt * 8 + t4 * 2;
                stg[rloc * 132 + col]           = out[mt][nt][0];
                stg[rloc * 132 + col + 1]       = out[mt][nt][1];
                stg[(rloc + 8) * 132 + col]     = out[mt][nt][2];
                stg[(rloc + 8) * 132 + col + 1] = out[mt][nt][3];
            }
        }
        __syncthreads();
        int col = tid & 127, grp = tid >> 7;
        int rbeg = grp * 32;
        int cur = -2; float acc = 0.f; float cnt = 0.f;
        #pragma unroll 4
        for (int r = rbeg; r < rbeg + 32; r++) {
            int b = bat_s[r];
            if (b != cur) {
                if (cur >= 0) {
                    atomicAdd(&g_sums[cur * 128 + col], acc);
                    if (col == 0) atomicAdd(&g_cnt[cur], cnt);
                }
                cur = b; acc = 0.f; cnt = 0.f;
            }
            if (b >= 0) { acc += stg[r * 132 + col]; cnt += 1.f; }
        }
        if (cur >= 0) {
            atomicAdd(&g_sums[cur * 128 + col], acc);
            if (col == 0) atomicAdd(&g_cnt[cur], cnt);
        }
    }
}

// ---------------- final linear + scratch cleanup (restores zero invariant) ----------------
__global__ void __launch_bounds__(256) k_final(const float* __restrict__ Wf,
                                               const float* __restrict__ bf,
                                               float* __restrict__ out) {
    int t = threadIdx.x;
    if (blockIdx.x >= NG) {
        int idx = (blockIdx.x - NG) * 256 + t;
        if (idx < Nn) { g_deg[idx] = 0; g_cursor[idx] = 0; }
        if (idx < 128) g_scanFlag[idx] = 0;
        return;
    }
    __shared__ float p[128];
    int g = blockIdx.x;
    float inv = 1.0f / fmaxf(g_cnt[g], 1.0f);
    if (t < 128) { p[t] = g_sums[g * 128 + t] * inv; g_sums[g * 128 + t] = 0.f; }
    __syncthreads();
    if (t == 0) g_cnt[g] = 0.f;
    if (t < OUTC) {
        float acc = bf[t];
        #pragma unroll 16
        for (int k = 0; k < 128; k++)
            acc += p[k] * Wf[k * OUTC + t];
        out[g * OUTC + t] = acc;
    }
}

// ---------------- launch ----------------
extern "C" void kernel_launch(void* const* d_in, const int* in_sizes, int n_in,
                              void* d_out, int out_size) {
    const float* x     = (const float*)d_in[0];
    const float* top   = (const float*)d_in[1];
    const int*   ei    = (const int*)d_in[2];
    const int*   batch = (const int*)d_in[3];
    const float* W0    = (const float*)d_in[4];
    const float* b0    = (const float*)d_in[5];
    const float* Wg0   = (const float*)d_in[6];
    const float* W1    = (const float*)d_in[7];
    const float* b1    = (const float*)d_in[8];
    const float* Wg1   = (const float*)d_in[9];
    const float* Wf    = (const float*)d_in[10];
    const float* bf    = (const float*)d_in[11];
    float*       out   = (float*)d_out;

    cudaFuncSetAttribute(k_gemm_mma, cudaFuncAttributeMaxDynamicSharedMemorySize, SMEM_MM);

    float* bufB;
    cudaGetSymbolAddress((void**)&bufB, g_bufB);

    const int gemmGrid = (Nn + 127) / 128;   // 391

    k_init<<<(Ee + 255) / 256, 256>>>(W0, W1, top, Wg0, Wg1, ei);           // 0
    k_scan<<<98, 512>>>();                                                  // 1
    k_fill<<<(Ee + 255) / 256, 256>>>(ei);                                  // 2
    k_agg<<<3125, 256>>>(x);                                                // 3
    k_gemm_mma<<<gemmGrid, 512, SMEM_MM>>>(b0, batch, 0);                   // 4
    k_agg<<<3125, 256>>>(bufB);                                             // 5 (profiled)
    k_gemm_mma<<<gemmGrid, 512, SMEM_MM>>>(b1, batch, 1);                   // 6
    k_final<<<NG + 196, 256>>>(Wf, bf, out);                                // 7
}

// round 12
// speedup vs baseline: 1.6482x; 1.6482x over previous
#include <cuda_runtime.h>
#include <cuda_bf16.h>
#include <cstdint>

#define Nn   50000
#define Ee   800000
#define HID  128
#define OUTC 64
#define NG   64
#define TEMP_INV (1.0f/101.0f)

// ---------------- scratch (all zero at load; k_final tail restores zeros) ----------------
static __device__ int    g_deg[Nn];
static __device__ float  g_dinv[Nn];
static __device__ int    g_rowptr[Nn + 1];
static __device__ int    g_cursor[Nn];
static __device__ __align__(8) int2 g_edge[Ee];     // (src row byte-offset (bf16 row=256B), dinv bits)
static __device__ float  g_gate0[Nn * 3];
static __device__ float  g_gate1[Nn * 3];
static __device__ float  g_bufA[Nn * HID];          // agg output (fp32)
static __device__ float  g_sums[NG * HID];
static __device__ float  g_cnt[NG];
static __device__ int    g_scanFlag[128];
static __device__ int    g_scanAgg[128];
// bf16 node-feature buffers for the gather phase
static __device__ __align__(16) __nv_bfloat16 g_xbf[Nn * HID];
static __device__ __align__(16) __nv_bfloat16 g_hbf[Nn * HID];
// bf16 split transposed weights: [L][e][n][k], hi and lo
static __device__ __align__(16) __nv_bfloat16 g_Wh[2 * 3 * 128 * 128];
static __device__ __align__(16) __nv_bfloat16 g_Wl[2 * 3 * 128 * 128];

__device__ __forceinline__ uint32_t smem_u32(const void* p) {
    uint32_t a;
    asm("{ .reg .u64 t; cvta.to.shared.u64 t, %1; cvt.u32.u64 %0, t; }" : "=r"(a) : "l"(p));
    return a;
}

// ---------------- fused init: x->bf16 + weight split + gates + degree hist ----------------
__global__ void k_init(const float* __restrict__ x,
                       const float* __restrict__ W0, const float* __restrict__ W1,
                       const float* __restrict__ top,
                       const float* __restrict__ Wg0, const float* __restrict__ Wg1,
                       const int* __restrict__ ei) {
    int i = blockIdx.x * blockDim.x + threadIdx.x;
    if (i < Nn * 32) {
        float4 v = ((const float4*)x)[i];
        __nv_bfloat16 b[4] = {__float2bfloat16_rn(v.x), __float2bfloat16_rn(v.y),
                              __float2bfloat16_rn(v.z), __float2bfloat16_rn(v.w)};
        *(uint2*)&g_xbf[i * 4] = *(uint2*)b;
    }
    if (i < 2 * 3 * 16384) {
        int L = i / 49152, rem = i % 49152;
        int e = rem / 16384, nk = rem % 16384;
        int n = nk >> 7, k = nk & 127;
        const float* W = L ? W1 : W0;
        float w = W[e * 16384 + k * 128 + n];
        __nv_bfloat16 hi = __float2bfloat16_rn(w);
        g_Wh[i] = hi;
        g_Wl[i] = __float2bfloat16_rn(w - __bfloat162float(hi));
    }
    if (i < Ee) atomicAdd(&g_deg[ei[Ee + i]], 1);
    if (i < Nn) {
        float t0 = top[i*4+0], t1 = top[i*4+1], t2 = top[i*4+2], t3 = top[i*4+3];
        #pragma unroll
        for (int L = 0; L < 2; L++) {
            const float* Wg = L ? Wg1 : Wg0;
            float* gate = L ? g_gate1 : g_gate0;
            float l[3];
            #pragma unroll
            for (int e = 0; e < 3; e++)
                l[e] = (t0*Wg[e*4+0] + t1*Wg[e*4+1] + t2*Wg[e*4+2] + t3*Wg[e*4+3]) * TEMP_INV;
            float mx = fmaxf(l[0], fmaxf(l[1], l[2]));
            float e0 = expf(l[0]-mx), e1 = expf(l[1]-mx), e2 = expf(l[2]-mx);
            float inv = 1.0f / (e0 + e1 + e2);
            gate[i*3+0] = e0*inv; gate[i*3+1] = e1*inv; gate[i*3+2] = e2*inv;
        }
    }
}

// ---------------- single-kernel scan (decoupled lookback) + dinv ----------------
__global__ void __launch_bounds__(512) k_scan() {
    int b = blockIdx.x, t = threadIdx.x;
    int i = b * 512 + t;
    int v = (i < Nn) ? g_deg[i] : 0;
    int lane = t & 31, w = t >> 5;
    int x = v;
    #pragma unroll
    for (int d = 1; d < 32; d <<= 1) {
        int y = __shfl_up_sync(0xFFFFFFFFu, x, d);
        if (lane >= d) x += y;
    }
    __shared__ int wsum[16];
    __shared__ int pref;
    if (lane == 31) wsum[w] = x;
    __syncthreads();
    if (w == 0) {
        int s = (lane < 16) ? wsum[lane] : 0;
        #pragma unroll
        for (int d = 1; d < 16; d <<= 1) {
            int y = __shfl_up_sync(0xFFFFFFFFu, s, d);
            if (lane >= d) s += y;
        }
        if (lane < 16) wsum[lane] = s;
        if (lane == 15) {
            atomicExch(&g_scanAgg[b], s);
            __threadfence();
            atomicExch(&g_scanFlag[b], 1);
        }
    }
    __syncthreads();
    int incl = x + (w ? wsum[w - 1] : 0);
    if (w == 0) {
        int sum = 0;
        for (int base = b - 1; base >= 0; base -= 32) {
            int j = base - lane;
            int a = 0;
            if (j >= 0) {
                while (atomicAdd(&g_scanFlag[j], 0) == 0) { }
                a = atomicAdd(&g_scanAgg[j], 0);
            }
            #pragma unroll
            for (int d = 16; d; d >>= 1) a += __shfl_down_sync(0xFFFFFFFFu, a, d);
            sum += __shfl_sync(0xFFFFFFFFu, a, 0);
        }
        if (lane == 0) pref = sum;
    }
    __syncthreads();
    if (i < Nn) {
        g_rowptr[i + 1] = incl + pref;
        g_dinv[i] = rsqrtf((float)(v + 1));
    }
    if (i == 0) g_rowptr[0] = 0;
}

__global__ void k_fill(const int* __restrict__ ei) {
    int i = blockIdx.x * blockDim.x + threadIdx.x;
    if (i >= Ee) return;
    int s = ei[i], d = ei[Ee + i];
    int p = g_rowptr[d] + atomicAdd(&g_cursor[d], 1);
    g_edge[p] = make_int2(s * 256, __float_as_int(g_dinv[s]));   // byte offset of bf16 row
}

// ---------------- CSR aggregation (bf16 gather, 2 nodes/warp) — R10-proven ----------------
__global__ void __launch_bounds__(256) k_agg(const __nv_bfloat16* __restrict__ hsrc) {
    int gw = (blockIdx.x * 256 + threadIdx.x) >> 5;   // warp id, < 25000
    int lane = threadIdx.x & 31;
    int half = lane >> 4, l16 = lane & 15;
    int node = gw * 2 + half;                          // < 50000 always
    float dd = g_dinv[node];
    const char* base = (const char*)hsrc + l16 * 16;   // this lane's 16B slice

    uint4 sv = *(const uint4*)(base + node * 256);
    float acc[8];
    {
        float2 c0 = __bfloat1622float2(*(__nv_bfloat162*)&sv.x);
        float2 c1 = __bfloat1622float2(*(__nv_bfloat162*)&sv.y);
        float2 c2 = __bfloat1622float2(*(__nv_bfloat162*)&sv.z);
        float2 c3 = __bfloat1622float2(*(__nv_bfloat162*)&sv.w);
        float s2 = dd * dd;
        acc[0]=c0.x*s2; acc[1]=c0.y*s2; acc[2]=c1.x*s2; acc[3]=c1.y*s2;
        acc[4]=c2.x*s2; acc[5]=c2.y*s2; acc[6]=c3.x*s2; acc[7]=c3.y*s2;
    }
    int j0 = g_rowptr[node], j1 = g_rowptr[node + 1];
    #pragma unroll 2
    for (int j = j0; j < j1; j++) {
        int2 ed = __ldg(&g_edge[j]);
        float wt = dd * __int_as_float(ed.y);
        uint4 u = __ldg((const uint4*)(base + ed.x));
        float2 c0 = __bfloat1622float2(*(__nv_bfloat162*)&u.x);
        float2 c1 = __bfloat1622float2(*(__nv_bfloat162*)&u.y);
        float2 c2 = __bfloat1622float2(*(__nv_bfloat162*)&u.z);
        float2 c3 = __bfloat1622float2(*(__nv_bfloat162*)&u.w);
        acc[0]+=wt*c0.x; acc[1]+=wt*c0.y; acc[2]+=wt*c1.x; acc[3]+=wt*c1.y;
        acc[4]+=wt*c2.x; acc[5]+=wt*c2.y; acc[6]+=wt*c3.x; acc[7]+=wt*c3.y;
    }
    float4* o = (float4*)&g_bufA[node * 128 + l16 * 8];
    o[0] = make_float4(acc[0], acc[1], acc[2], acc[3]);
    o[1] = make_float4(acc[4], acc[5], acc[6], acc[7]);
}

// ---------------- mma.sync bf16-split fused MoE GEMM (cp.async + LDSM) ----------------
#define SMA_HI  0
#define SMA_LO  32768
#define SMB0    65536
#define SMB1    131072
#define SM_BIAS 196608
#define SM_GATE (196608 + 1536)
#define SM_BAT  (196608 + 3072)
#define SMEM_MM (196608 + 3072 + 512)
#define SM_STG  SMB0

#define AOFF(row, k) ((row) * 256 + (((((k) >> 3) ^ ((row) & 7))) << 4) + (((k) & 7) << 1))

__device__ __forceinline__ void mma_bf16(float* c, const uint32_t* a, const uint32_t* b) {
    asm volatile("mma.sync.aligned.m16n8k16.row.col.f32.bf16.bf16.f32 "
        "{%0,%1,%2,%3}, {%4,%5,%6,%7}, {%8,%9}, {%0,%1,%2,%3};"
        : "+f"(c[0]), "+f"(c[1]), "+f"(c[2]), "+f"(c[3])
        : "r"(a[0]), "r"(a[1]), "r"(a[2]), "r"(a[3]), "r"(b[0]), "r"(b[1]));
}

#define LDSM4(r0, r1, r2, r3, addr) \
    asm volatile("ldmatrix.sync.aligned.m8n8.x4.shared.b16 {%0,%1,%2,%3}, [%4];" \
        : "=r"(r0), "=r"(r1), "=r"(r2), "=r"(r3) : "r"(addr))

__device__ __forceinline__ void cp16(uint32_t dst, const void* src) {
    asm volatile("cp.async.cg.shared.global [%0], [%1], 16;" :: "r"(dst), "l"(src));
}

__device__ __forceinline__ void issueB(uint32_t smb, int stagebase,
                                       int layer, int e, int tid) {
    const uint4* bh = (const uint4*)(g_Wh + (layer * 3 + e) * 16384);
    const uint4* bl = (const uint4*)(g_Wl + (layer * 3 + e) * 16384);
    #pragma unroll
    for (int it = 0; it < 4; it++) {
        int idx = it * 512 + tid;
        int n = idx >> 4, kc = idx & 15;
        int off = n * 256 + ((kc ^ (n & 7)) << 4);
        cp16(smb + stagebase + off,         bh + idx);
        cp16(smb + stagebase + 32768 + off, bl + idx);
    }
    asm volatile("cp.async.commit_group;");
}

__global__ void __launch_bounds__(512) k_gemm_mma(const float* __restrict__ bias3,
                                                  const int* __restrict__ batch,
                                                  int layer) {
    extern __shared__ __align__(16) char smc[];
    const uint32_t smb = smem_u32(smc);
    const int tid = threadIdx.x;
    const int baseM = blockIdx.x * 128;
    const float* gate = layer ? g_gate1 : g_gate0;
    float* bias_s = (float*)(smc + SM_BIAS);
    float* gate_s = (float*)(smc + SM_GATE);
    int*   bat_s  = (int*)(smc + SM_BAT);

    issueB(smb, SMB0, layer, 0, tid);

    if (tid < 384) {
        bias_s[tid] = bias3[tid];
        int gi = baseM * 3 + tid;
        gate_s[tid] = (gi < Nn * 3) ? gate[gi] : 0.f;
    }
    if (layer && tid >= 384 && tid < 512) {
        int r = tid - 384;
        int nn = baseM + r;
        bat_s[r] = (nn < Nn) ? batch[nn] : -1;
    }

    // ---- build A tile (bf16 hi/lo, swizzled) from fp32 bufA ----
    #pragma unroll
    for (int it = 0; it < 4; it++) {
        int idx = it * 512 + tid;
        int row = idx >> 4, kc = idx & 15;
        int grow = baseM + row;
        float4 v0 = make_float4(0.f,0.f,0.f,0.f), v1 = v0;
        if (grow < Nn) {
            const float4* p = (const float4*)(g_bufA + grow * 128 + kc * 8);
            v0 = p[0]; v1 = p[1];
        }
        float f[8] = {v0.x, v0.y, v0.z, v0.w, v1.x, v1.y, v1.z, v1.w};
        __nv_bfloat16 h[8], l[8];
        #pragma unroll
        for (int j = 0; j < 8; j++) {
            h[j] = __float2bfloat16_rn(f[j]);
            l[j] = __float2bfloat16_rn(f[j] - __bfloat162float(h[j]));
        }
        int off = row * 256 + ((kc ^ (row & 7)) << 4);
        *(uint4*)(smc + SMA_HI + off) = *(uint4*)h;
        *(uint4*)(smc + SMA_LO + off) = *(uint4*)l;
    }

    const int lane = tid & 31, wid = tid >> 5;
    const int warpM = wid >> 2, warpN = wid & 3;
    const int g = lane >> 2, t4 = lane & 3;

    // LDSM per-lane address precompute
    const int arow = warpM * 32 + (lane & 15);          // A rows for matrices (mt adds +16)
    const uint32_t aBase = smb + SMA_HI + (uint32_t)(arow * 256);
    const int sA = arow & 7;
    const int koffA = lane >> 4;                        // 0: k-chunk lo, 1: k-chunk hi
    const int brow = warpN * 32 + lane;                 // B rows: 32 rows = 4 nt-matrices
    const uint32_t bBase = smb + (uint32_t)(brow * 256);
    const int sB = brow & 7;

    float out[2][4][4];
    #pragma unroll
    for (int mt = 0; mt < 2; mt++)
        #pragma unroll
        for (int nt = 0; nt < 4; nt++)
            #pragma unroll
            for (int j = 0; j < 4; j++) out[mt][nt][j] = 0.f;

    #pragma unroll 1
    for (int e = 0; e < 3; e++) {
        __syncthreads();
        if (e < 2) issueB(smb, (e & 1) ? SMB0 : SMB1, layer, e + 1, tid);
        if (e < 2) { asm volatile("cp.async.wait_group 1;"); }
        else       { asm volatile("cp.async.wait_group 0;"); }
        __syncthreads();

        const uint32_t sbOff = (e & 1) ? SMB1 : SMB0;

        float acc[2][4][4];
        #pragma unroll
        for (int mt = 0; mt < 2; mt++)
            #pragma unroll
            for (int nt = 0; nt < 4; nt++)
                #pragma unroll
                for (int j = 0; j < 4; j++) acc[mt][nt][j] = 0.f;

        #pragma unroll
        for (int ks = 0; ks < 8; ks++) {
            uint32_t afh[2][4], afl[2][4], bfh[4][2], bfl[4][2];
            // A fragments: x4 = {rows 0-7, rows 8-15} x {kc, kc+1} per mt
            uint32_t offA = (uint32_t)((((ks << 1) + koffA) ^ sA) << 4);
            uint32_t aH0 = aBase + offA;
            LDSM4(afh[0][0], afh[0][1], afh[0][2], afh[0][3], aH0);
            LDSM4(afh[1][0], afh[1][1], afh[1][2], afh[1][3], aH0 + 4096);
            LDSM4(afl[0][0], afl[0][1], afl[0][2], afl[0][3], aH0 + 32768);
            LDSM4(afl[1][0], afl[1][1], afl[1][2], afl[1][3], aH0 + 36864);
            // B fragments: x4 covers all 4 nt at one k-chunk
            uint32_t offB0 = (uint32_t)(((ks << 1) ^ sB) << 4);
            uint32_t bH0 = bBase + sbOff + offB0;
            uint32_t bH1 = bH0 ^ 16;      // kc+1 (xor since kc0 even)
            LDSM4(bfh[0][0], bfh[1][0], bfh[2][0], bfh[3][0], bH0);
            LDSM4(bfh[0][1], bfh[1][1], bfh[2][1], bfh[3][1], bH1);
            LDSM4(bfl[0][0], bfl[1][0], bfl[2][0], bfl[3][0], bH0 + 32768);
            LDSM4(bfl[0][1], bfl[1][1], bfl[2][1], bfl[3][1], bH1 + 32768);

            #pragma unroll
            for (int mt = 0; mt < 2; mt++)
                #pragma unroll
                for (int nt = 0; nt < 4; nt++) {
                    mma_bf16(acc[mt][nt], afh[mt], bfh[nt]);
                    mma_bf16(acc[mt][nt], afl[mt], bfh[nt]);
                    mma_bf16(acc[mt][nt], afh[mt], bfl[nt]);
                }
        }

        #pragma unroll
        for (int mt = 0; mt < 2; mt++) {
            int rloc = warpM * 32 + mt * 16 + g;
            float g0 = gate_s[rloc * 3 + e];
            float g1 = gate_s[(rloc + 8) * 3 + e];
            #pragma unroll
            for (int nt = 0; nt < 4; nt++) {
                int col = warpN * 32 + nt * 8 + t4 * 2;
                float bb0 = bias_s[e * 128 + col], bb1 = bias_s[e * 128 + col + 1];
                out[mt][nt][0] += g0 * fmaxf(acc[mt][nt][0] + bb0, 0.f);
                out[mt][nt][1] += g0 * fmaxf(acc[mt][nt][1] + bb1, 0.f);
                out[mt][nt][2] += g1 * fmaxf(acc[mt][nt][2] + bb0, 0.f);
                out[mt][nt][3] += g1 * fmaxf(acc[mt][nt][3] + bb1, 0.f);
            }
        }
    }

    if (!layer) {
        // ---- layer 0: write h as bf16 for the next gather ----
        #pragma unroll
        for (int mt = 0; mt < 2; mt++) {
            int r0 = baseM + warpM * 32 + mt * 16 + g;
            #pragma unroll
            for (int nt = 0; nt < 4; nt++) {
                int col = warpN * 32 + nt * 8 + t4 * 2;
                __nv_bfloat16 p0[2] = {__float2bfloat16_rn(out[mt][nt][0]),
                                       __float2bfloat16_rn(out[mt][nt][1])};
                __nv_bfloat16 p1[2] = {__float2bfloat16_rn(out[mt][nt][2]),
                                       __float2bfloat16_rn(out[mt][nt][3])};
                if (r0 < Nn)     *(uint32_t*)&g_hbf[r0 * 128 + col]       = *(uint32_t*)p0;
                if (r0 + 8 < Nn) *(uint32_t*)&g_hbf[(r0 + 8) * 128 + col] = *(uint32_t*)p1;
            }
        }
    } else {
        // ---- layer 1: fused pooling via smem staging + segment scan ----
        __syncthreads();
        float* stg = (float*)(smc + SM_STG);
        #pragma unroll
        for (int mt = 0; mt < 2; mt++) {
            int rloc = warpM * 32 + mt * 16 + g;
            #pragma unroll
            for (int nt = 0; nt < 4; nt++) {
                int col = warpN * 32 + nt * 8 + t4 * 2;
                stg[rloc * 132 + col]           = out[mt][nt][0];
                stg[rloc * 132 + col + 1]       = out[mt][nt][1];
                stg[(rloc + 8) * 132 + col]     = out[mt][nt][2];
                stg[(rloc + 8) * 132 + col + 1] = out[mt][nt][3];
            }
        }
        __syncthreads();
        int col = tid & 127, grp = tid >> 7;
        int rbeg = grp * 32;
        int cur = -2; float acc = 0.f; float cnt = 0.f;
        #pragma unroll 4
        for (int r = rbeg; r < rbeg + 32; r++) {
            int b = bat_s[r];
            if (b != cur) {
                if (cur >= 0) {
                    atomicAdd(&g_sums[cur * 128 + col], acc);
                    if (col == 0) atomicAdd(&g_cnt[cur], cnt);
                }
                cur = b; acc = 0.f; cnt = 0.f;
            }
            if (b >= 0) { acc += stg[r * 132 + col]; cnt += 1.f; }
        }
        if (cur >= 0) {
            atomicAdd(&g_sums[cur * 128 + col], acc);
            if (col == 0) atomicAdd(&g_cnt[cur], cnt);
        }
    }
}

// ---------------- final linear + scratch cleanup (restores zero invariant) ----------------
__global__ void __launch_bounds__(256) k_final(const float* __restrict__ Wf,
                                               const float* __restrict__ bf,
                                               float* __restrict__ out) {
    int t = threadIdx.x;
    if (blockIdx.x >= NG) {
        int idx = (blockIdx.x - NG) * 256 + t;
        if (idx < Nn) { g_deg[idx] = 0; g_cursor[idx] = 0; }
        if (idx < 128) g_scanFlag[idx] = 0;
        return;
    }
    __shared__ float p[128];
    int g = blockIdx.x;
    float inv = 1.0f / fmaxf(g_cnt[g], 1.0f);
    if (t < 128) { p[t] = g_sums[g * 128 + t] * inv; g_sums[g * 128 + t] = 0.f; }
    __syncthreads();
    if (t == 0) g_cnt[g] = 0.f;
    if (t < OUTC) {
        float acc = bf[t];
        #pragma unroll 16
        for (int k = 0; k < 128; k++)
            acc += p[k] * Wf[k * OUTC + t];
        out[g * OUTC + t] = acc;
    }
}

// ---------------- launch ----------------
extern "C" void kernel_launch(void* const* d_in, const int* in_sizes, int n_in,
                              void* d_out, int out_size) {
    const float* x     = (const float*)d_in[0];
    const float* top   = (const float*)d_in[1];
    const int*   ei    = (const int*)d_in[2];
    const int*   batch = (const int*)d_in[3];
    const float* W0    = (const float*)d_in[4];
    const float* b0    = (const float*)d_in[5];
    const float* Wg0   = (const float*)d_in[6];
    const float* W1    = (const float*)d_in[7];
    const float* b1    = (const float*)d_in[8];
    const float* Wg1   = (const float*)d_in[9];
    const float* Wf    = (const float*)d_in[10];
    const float* bf    = (const float*)d_in[11];
    float*       out   = (float*)d_out;

    cudaFuncSetAttribute(k_gemm_mma, cudaFuncAttributeMaxDynamicSharedMemorySize, SMEM_MM);

    const __nv_bfloat16* xbf; const __nv_bfloat16* hbf;
    cudaGetSymbolAddress((void**)&xbf, g_xbf);
    cudaGetSymbolAddress((void**)&hbf, g_hbf);

    const int gemmGrid = (Nn + 127) / 128;   // 391

    k_init<<<(Nn * 32 + 255) / 256, 256>>>(x, W0, W1, top, Wg0, Wg1, ei);   // 0
    k_scan<<<98, 512>>>();                                                  // 1
    k_fill<<<(Ee + 255) / 256, 256>>>(ei);                                  // 2
    k_agg<<<3125, 256>>>(xbf);                                              // 3
    k_gemm_mma<<<gemmGrid, 512, SMEM_MM>>>(b0, batch, 0);                   // 4
    k_agg<<<3125, 256>>>(hbf);                                              // 5 (profiled)
    k_gemm_mma<<<gemmGrid, 512, SMEM_MM>>>(b1, batch, 1);                   // 6
    k_final<<<NG + 196, 256>>>(Wf, bf, out);                                // 7
}

// round 13
// speedup vs baseline: 1.6888x; 1.0246x over previous
#include <cuda_runtime.h>
#include <cuda_bf16.h>
#include <cstdint>

#define Nn   50000
#define Ee   800000
#define HID  128
#define OUTC 64
#define NG   64
#define TEMP_INV (1.0f/101.0f)

// ---------------- scratch (all zero at load; k_final tail restores zeros) ----------------
static __device__ int    g_deg[Nn];
static __device__ float  g_dinv[Nn];
static __device__ int    g_rowptr[Nn + 1];
static __device__ int    g_cursor[Nn];
static __device__ __align__(8) int2 g_edge[Ee];     // (src row byte-offset (bf16 row=256B), dinv bits)
static __device__ float  g_gate0[Nn * 3];
static __device__ float  g_gate1[Nn * 3];
static __device__ float  g_bufA[Nn * HID];          // agg output (fp32)
static __device__ float  g_sums[NG * HID];
static __device__ float  g_cnt[NG];
static __device__ int    g_scanFlag[128];
static __device__ int    g_scanAgg[128];
// bf16 node-feature buffers for the gather phase
static __device__ __align__(16) __nv_bfloat16 g_xbf[Nn * HID];
static __device__ __align__(16) __nv_bfloat16 g_hbf[Nn * HID];
// bf16 split transposed weights: [L][e][n][k], hi and lo
static __device__ __align__(16) __nv_bfloat16 g_Wh[2 * 3 * 128 * 128];
static __device__ __align__(16) __nv_bfloat16 g_Wl[2 * 3 * 128 * 128];

__device__ __forceinline__ uint32_t smem_u32(const void* p) {
    uint32_t a;
    asm("{ .reg .u64 t; cvta.to.shared.u64 t, %1; cvt.u32.u64 %0, t; }" : "=r"(a) : "l"(p));
    return a;
}

// dummy no-op so the ncu capture (-s 5 -c 1) lands on k_gemm_mma layer 0
__global__ void k_nop() {}

// ---------------- fused init: x->bf16 + weight split + gates + degree hist ----------------
__global__ void k_init(const float* __restrict__ x,
                       const float* __restrict__ W0, const float* __restrict__ W1,
                       const float* __restrict__ top,
                       const float* __restrict__ Wg0, const float* __restrict__ Wg1,
                       const int* __restrict__ ei) {
    int i = blockIdx.x * blockDim.x + threadIdx.x;
    if (i < Nn * 32) {
        float4 v = ((const float4*)x)[i];
        __nv_bfloat16 b[4] = {__float2bfloat16_rn(v.x), __float2bfloat16_rn(v.y),
                              __float2bfloat16_rn(v.z), __float2bfloat16_rn(v.w)};
        *(uint2*)&g_xbf[i * 4] = *(uint2*)b;
    }
    if (i < 2 * 3 * 16384) {
        int L = i / 49152, rem = i % 49152;
        int e = rem / 16384, nk = rem % 16384;
        int n = nk >> 7, k = nk & 127;
        const float* W = L ? W1 : W0;
        float w = W[e * 16384 + k * 128 + n];
        __nv_bfloat16 hi = __float2bfloat16_rn(w);
        g_Wh[i] = hi;
        g_Wl[i] = __float2bfloat16_rn(w - __bfloat162float(hi));
    }
    if (i < Ee) atomicAdd(&g_deg[ei[Ee + i]], 1);
    if (i < Nn) {
        float t0 = top[i*4+0], t1 = top[i*4+1], t2 = top[i*4+2], t3 = top[i*4+3];
        #pragma unroll
        for (int L = 0; L < 2; L++) {
            const float* Wg = L ? Wg1 : Wg0;
            float* gate = L ? g_gate1 : g_gate0;
            float l[3];
            #pragma unroll
            for (int e = 0; e < 3; e++)
                l[e] = (t0*Wg[e*4+0] + t1*Wg[e*4+1] + t2*Wg[e*4+2] + t3*Wg[e*4+3]) * TEMP_INV;
            float mx = fmaxf(l[0], fmaxf(l[1], l[2]));
            float e0 = expf(l[0]-mx), e1 = expf(l[1]-mx), e2 = expf(l[2]-mx);
            float inv = 1.0f / (e0 + e1 + e2);
            gate[i*3+0] = e0*inv; gate[i*3+1] = e1*inv; gate[i*3+2] = e2*inv;
        }
    }
}

// ---------------- single-kernel scan (decoupled lookback) + dinv ----------------
__global__ void __launch_bounds__(512) k_scan() {
    int b = blockIdx.x, t = threadIdx.x;
    int i = b * 512 + t;
    int v = (i < Nn) ? g_deg[i] : 0;
    int lane = t & 31, w = t >> 5;
    int x = v;
    #pragma unroll
    for (int d = 1; d < 32; d <<= 1) {
        int y = __shfl_up_sync(0xFFFFFFFFu, x, d);
        if (lane >= d) x += y;
    }
    __shared__ int wsum[16];
    __shared__ int pref;
    if (lane == 31) wsum[w] = x;
    __syncthreads();
    if (w == 0) {
        int s = (lane < 16) ? wsum[lane] : 0;
        #pragma unroll
        for (int d = 1; d < 16; d <<= 1) {
            int y = __shfl_up_sync(0xFFFFFFFFu, s, d);
            if (lane >= d) s += y;
        }
        if (lane < 16) wsum[lane] = s;
        if (lane == 15) {
            atomicExch(&g_scanAgg[b], s);
            __threadfence();
            atomicExch(&g_scanFlag[b], 1);
        }
    }
    __syncthreads();
    int incl = x + (w ? wsum[w - 1] : 0);
    if (w == 0) {
        int sum = 0;
        for (int base = b - 1; base >= 0; base -= 32) {
            int j = base - lane;
            int a = 0;
            if (j >= 0) {
                while (atomicAdd(&g_scanFlag[j], 0) == 0) { }
                a = atomicAdd(&g_scanAgg[j], 0);
            }
            #pragma unroll
            for (int d = 16; d; d >>= 1) a += __shfl_down_sync(0xFFFFFFFFu, a, d);
            sum += __shfl_sync(0xFFFFFFFFu, a, 0);
        }
        if (lane == 0) pref = sum;
    }
    __syncthreads();
    if (i < Nn) {
        g_rowptr[i + 1] = incl + pref;
        g_dinv[i] = rsqrtf((float)(v + 1));
    }
    if (i == 0) g_rowptr[0] = 0;
}

__global__ void k_fill(const int* __restrict__ ei) {
    int i = blockIdx.x * blockDim.x + threadIdx.x;
    if (i >= Ee) return;
    int s = ei[i], d = ei[Ee + i];
    int p = g_rowptr[d] + atomicAdd(&g_cursor[d], 1);
    g_edge[p] = make_int2(s * 256, __float_as_int(g_dinv[s]));   // byte offset of bf16 row
}

// ---------------- CSR aggregation (bf16 gather, 2 nodes/warp) — R10-proven ----------------
__global__ void __launch_bounds__(256) k_agg(const __nv_bfloat16* __restrict__ hsrc) {
    int gw = (blockIdx.x * 256 + threadIdx.x) >> 5;   // warp id, < 25000
    int lane = threadIdx.x & 31;
    int half = lane >> 4, l16 = lane & 15;
    int node = gw * 2 + half;                          // < 50000 always
    float dd = g_dinv[node];
    const char* base = (const char*)hsrc + l16 * 16;   // this lane's 16B slice

    uint4 sv = *(const uint4*)(base + node * 256);
    float acc[8];
    {
        float2 c0 = __bfloat1622float2(*(__nv_bfloat162*)&sv.x);
        float2 c1 = __bfloat1622float2(*(__nv_bfloat162*)&sv.y);
        float2 c2 = __bfloat1622float2(*(__nv_bfloat162*)&sv.z);
        float2 c3 = __bfloat1622float2(*(__nv_bfloat162*)&sv.w);
        float s2 = dd * dd;
        acc[0]=c0.x*s2; acc[1]=c0.y*s2; acc[2]=c1.x*s2; acc[3]=c1.y*s2;
        acc[4]=c2.x*s2; acc[5]=c2.y*s2; acc[6]=c3.x*s2; acc[7]=c3.y*s2;
    }
    int j0 = g_rowptr[node], j1 = g_rowptr[node + 1];
    #pragma unroll 2
    for (int j = j0; j < j1; j++) {
        int2 ed = __ldg(&g_edge[j]);
        float wt = dd * __int_as_float(ed.y);
        uint4 u = __ldg((const uint4*)(base + ed.x));
        float2 c0 = __bfloat1622float2(*(__nv_bfloat162*)&u.x);
        float2 c1 = __bfloat1622float2(*(__nv_bfloat162*)&u.y);
        float2 c2 = __bfloat1622float2(*(__nv_bfloat162*)&u.z);
        float2 c3 = __bfloat1622float2(*(__nv_bfloat162*)&u.w);
        acc[0]+=wt*c0.x; acc[1]+=wt*c0.y; acc[2]+=wt*c1.x; acc[3]+=wt*c1.y;
        acc[4]+=wt*c2.x; acc[5]+=wt*c2.y; acc[6]+=wt*c3.x; acc[7]+=wt*c3.y;
    }
    float4* o = (float4*)&g_bufA[node * 128 + l16 * 8];
    o[0] = make_float4(acc[0], acc[1], acc[2], acc[3]);
    o[1] = make_float4(acc[4], acc[5], acc[6], acc[7]);
}

// ---------------- mma.sync bf16-split fused MoE GEMM (cp.async, scalar-LDS R10) ----------------
#define SMA_HI  0
#define SMA_LO  32768
#define SMB0    65536
#define SMB1    131072
#define SM_BIAS 196608
#define SM_GATE (196608 + 1536)
#define SM_BAT  (196608 + 3072)
#define SMEM_MM (196608 + 3072 + 512)
#define SM_STG  SMB0

#define AOFF(row, k) ((row) * 256 + (((((k) >> 3) ^ ((row) & 7))) << 4) + (((k) & 7) << 1))

__device__ __forceinline__ void mma_bf16(float* c, const uint32_t* a, const uint32_t* b) {
    asm volatile("mma.sync.aligned.m16n8k16.row.col.f32.bf16.bf16.f32 "
        "{%0,%1,%2,%3}, {%4,%5,%6,%7}, {%8,%9}, {%0,%1,%2,%3};"
        : "+f"(c[0]), "+f"(c[1]), "+f"(c[2]), "+f"(c[3])
        : "r"(a[0]), "r"(a[1]), "r"(a[2]), "r"(a[3]), "r"(b[0]), "r"(b[1]));
}

__device__ __forceinline__ void cp16(uint32_t dst, const void* src) {
    asm volatile("cp.async.cg.shared.global [%0], [%1], 16;" :: "r"(dst), "l"(src));
}

__device__ __forceinline__ void issueB(uint32_t smb, int stagebase,
                                       int layer, int e, int tid) {
    const uint4* bh = (const uint4*)(g_Wh + (layer * 3 + e) * 16384);
    const uint4* bl = (const uint4*)(g_Wl + (layer * 3 + e) * 16384);
    #pragma unroll
    for (int it = 0; it < 4; it++) {
        int idx = it * 512 + tid;
        int n = idx >> 4, kc = idx & 15;
        int off = n * 256 + ((kc ^ (n & 7)) << 4);
        cp16(smb + stagebase + off,         bh + idx);
        cp16(smb + stagebase + 32768 + off, bl + idx);
    }
    asm volatile("cp.async.commit_group;");
}

__global__ void __launch_bounds__(512) k_gemm_mma(const float* __restrict__ bias3,
                                                  const int* __restrict__ batch,
                                                  int layer) {
    extern __shared__ __align__(16) char smc[];
    const uint32_t smb = smem_u32(smc);
    const int tid = threadIdx.x;
    const int baseM = blockIdx.x * 128;
    const float* gate = layer ? g_gate1 : g_gate0;
    float* bias_s = (float*)(smc + SM_BIAS);
    float* gate_s = (float*)(smc + SM_GATE);
    int*   bat_s  = (int*)(smc + SM_BAT);

    issueB(smb, SMB0, layer, 0, tid);

    if (tid < 384) {
        bias_s[tid] = bias3[tid];
        int gi = baseM * 3 + tid;
        gate_s[tid] = (gi < Nn * 3) ? gate[gi] : 0.f;
    }
    if (layer && tid >= 384 && tid < 512) {
        int r = tid - 384;
        int nn = baseM + r;
        bat_s[r] = (nn < Nn) ? batch[nn] : -1;
    }

    // ---- build A tile (bf16 hi/lo, swizzled) from fp32 bufA ----
    #pragma unroll
    for (int it = 0; it < 4; it++) {
        int idx = it * 512 + tid;
        int row = idx >> 4, kc = idx & 15;
        int grow = baseM + row;
        float4 v0 = make_float4(0.f,0.f,0.f,0.f), v1 = v0;
        if (grow < Nn) {
            const float4* p = (const float4*)(g_bufA + grow * 128 + kc * 8);
            v0 = p[0]; v1 = p[1];
        }
        float f[8] = {v0.x, v0.y, v0.z, v0.w, v1.x, v1.y, v1.z, v1.w};
        __nv_bfloat16 h[8], l[8];
        #pragma unroll
        for (int j = 0; j < 8; j++) {
            h[j] = __float2bfloat16_rn(f[j]);
            l[j] = __float2bfloat16_rn(f[j] - __bfloat162float(h[j]));
        }
        int off = row * 256 + ((kc ^ (row & 7)) << 4);
        *(uint4*)(smc + SMA_HI + off) = *(uint4*)h;
        *(uint4*)(smc + SMA_LO + off) = *(uint4*)l;
    }

    const int lane = tid & 31, wid = tid >> 5;
    const int warpM = wid >> 2, warpN = wid & 3;
    const int g = lane >> 2, t4 = lane & 3;

    float out[2][4][4];
    #pragma unroll
    for (int mt = 0; mt < 2; mt++)
        #pragma unroll
        for (int nt = 0; nt < 4; nt++)
            #pragma unroll
            for (int j = 0; j < 4; j++) out[mt][nt][j] = 0.f;

    #pragma unroll 1
    for (int e = 0; e < 3; e++) {
        __syncthreads();
        if (e < 2) issueB(smb, (e & 1) ? SMB0 : SMB1, layer, e + 1, tid);
        if (e < 2) { asm volatile("cp.async.wait_group 1;"); }
        else       { asm volatile("cp.async.wait_group 0;"); }
        __syncthreads();

        const int sb  = (e & 1) ? SMB1 : SMB0;
        const int sbl = sb + 32768;

        float acc[2][4][4];
        #pragma unroll
        for (int mt = 0; mt < 2; mt++)
            #pragma unroll
            for (int nt = 0; nt < 4; nt++)
                #pragma unroll
                for (int j = 0; j < 4; j++) acc[mt][nt][j] = 0.f;

        #pragma unroll
        for (int ks = 0; ks < 8; ks++) {
            const int c0 = ks * 16 + t4 * 2;
            uint32_t afh[2][4], afl[2][4], bfh[4][2], bfl[4][2];
            #pragma unroll
            for (int mt = 0; mt < 2; mt++) {
                int r0 = warpM * 32 + mt * 16 + g;
                afh[mt][0] = *(const uint32_t*)(smc + SMA_HI + AOFF(r0,     c0));
                afh[mt][1] = *(const uint32_t*)(smc + SMA_HI + AOFF(r0 + 8, c0));
                afh[mt][2] = *(const uint32_t*)(smc + SMA_HI + AOFF(r0,     c0 + 8));
                afh[mt][3] = *(const uint32_t*)(smc + SMA_HI + AOFF(r0 + 8, c0 + 8));
                afl[mt][0] = *(const uint32_t*)(smc + SMA_LO + AOFF(r0,     c0));
                afl[mt][1] = *(const uint32_t*)(smc + SMA_LO + AOFF(r0 + 8, c0));
                afl[mt][2] = *(const uint32_t*)(smc + SMA_LO + AOFF(r0,     c0 + 8));
                afl[mt][3] = *(const uint32_t*)(smc + SMA_LO + AOFF(r0 + 8, c0 + 8));
            }
            #pragma unroll
            for (int nt = 0; nt < 4; nt++) {
                int n0 = warpN * 32 + nt * 8 + g;
                bfh[nt][0] = *(const uint32_t*)(smc + sb  + AOFF(n0, c0));
                bfh[nt][1] = *(const uint32_t*)(smc + sb  + AOFF(n0, c0 + 8));
                bfl[nt][0] = *(const uint32_t*)(smc + sbl + AOFF(n0, c0));
                bfl[nt][1] = *(const uint32_t*)(smc + sbl + AOFF(n0, c0 + 8));
            }
            #pragma unroll
            for (int mt = 0; mt < 2; mt++)
                #pragma unroll
                for (int nt = 0; nt < 4; nt++) {
                    mma_bf16(acc[mt][nt], afh[mt], bfh[nt]);
                    mma_bf16(acc[mt][nt], afl[mt], bfh[nt]);
                    mma_bf16(acc[mt][nt], afh[mt], bfl[nt]);
                }
        }

        #pragma unroll
        for (int mt = 0; mt < 2; mt++) {
            int rloc = warpM * 32 + mt * 16 + g;
            float g0 = gate_s[rloc * 3 + e];
            float g1 = gate_s[(rloc + 8) * 3 + e];
            #pragma unroll
            for (int nt = 0; nt < 4; nt++) {
                int col = warpN * 32 + nt * 8 + t4 * 2;
                float bb0 = bias_s[e * 128 + col], bb1 = bias_s[e * 128 + col + 1];
                out[mt][nt][0] += g0 * fmaxf(acc[mt][nt][0] + bb0, 0.f);
                out[mt][nt][1] += g0 * fmaxf(acc[mt][nt][1] + bb1, 0.f);
                out[mt][nt][2] += g1 * fmaxf(acc[mt][nt][2] + bb0, 0.f);
                out[mt][nt][3] += g1 * fmaxf(acc[mt][nt][3] + bb1, 0.f);
            }
        }
    }

    if (!layer) {
        // ---- layer 0: write h as bf16 for the next gather ----
        #pragma unroll
        for (int mt = 0; mt < 2; mt++) {
            int r0 = baseM + warpM * 32 + mt * 16 + g;
            #pragma unroll
            for (int nt = 0; nt < 4; nt++) {
                int col = warpN * 32 + nt * 8 + t4 * 2;
                __nv_bfloat16 p0[2] = {__float2bfloat16_rn(out[mt][nt][0]),
                                       __float2bfloat16_rn(out[mt][nt][1])};
                __nv_bfloat16 p1[2] = {__float2bfloat16_rn(out[mt][nt][2]),
                                       __float2bfloat16_rn(out[mt][nt][3])};
                if (r0 < Nn)     *(uint32_t*)&g_hbf[r0 * 128 + col]       = *(uint32_t*)p0;
                if (r0 + 8 < Nn) *(uint32_t*)&g_hbf[(r0 + 8) * 128 + col] = *(uint32_t*)p1;
            }
        }
    } else {
        // ---- layer 1: fused pooling via smem staging + segment scan ----
        __syncthreads();
        float* stg = (float*)(smc + SM_STG);
        #pragma unroll
        for (int mt = 0; mt < 2; mt++) {
            int rloc = warpM * 32 + mt * 16 + g;
            #pragma unroll
            for (int nt = 0; nt < 4; nt++) {
                int col = warpN * 32 + nt * 8 + t4 * 2;
                stg[rloc * 132 + col]           = out[mt][nt][0];
                stg[rloc * 132 + col + 1]       = out[mt][nt][1];
                stg[(rloc + 8) * 132 + col]     = out[mt][nt][2];
                stg[(rloc + 8) * 132 + col + 1] = out[mt][nt][3];
            }
        }
        __syncthreads();
        int col = tid & 127, grp = tid >> 7;
        int rbeg = grp * 32;
        int cur = -2; float acc = 0.f; float cnt = 0.f;
        #pragma unroll 4
        for (int r = rbeg; r < rbeg + 32; r++) {
            int b = bat_s[r];
            if (b != cur) {
                if (cur >= 0) {
                    atomicAdd(&g_sums[cur * 128 + col], acc);
                    if (col == 0) atomicAdd(&g_cnt[cur], cnt);
                }
                cur = b; acc = 0.f; cnt = 0.f;
            }
            if (b >= 0) { acc += stg[r * 132 + col]; cnt += 1.f; }
        }
        if (cur >= 0) {
            atomicAdd(&g_sums[cur * 128 + col], acc);
            if (col == 0) atomicAdd(&g_cnt[cur], cnt);
        }
    }
}

// ---------------- final linear + scratch cleanup (restores zero invariant) ----------------
__global__ void __launch_bounds__(256) k_final(const float* __restrict__ Wf,
                                               const float* __restrict__ bf,
                                               float* __restrict__ out) {
    int t = threadIdx.x;
    if (blockIdx.x >= NG) {
        int idx = (blockIdx.x - NG) * 256 + t;
        if (idx < Nn) { g_deg[idx] = 0; g_cursor[idx] = 0; }
        if (idx < 128) g_scanFlag[idx] = 0;
        return;
    }
    __shared__ float p[128];
    int g = blockIdx.x;
    float inv = 1.0f / fmaxf(g_cnt[g], 1.0f);
    if (t < 128) { p[t] = g_sums[g * 128 + t] * inv; g_sums[g * 128 + t] = 0.f; }
    __syncthreads();
    if (t == 0) g_cnt[g] = 0.f;
    if (t < OUTC) {
        float acc = bf[t];
        #pragma unroll 16
        for (int k = 0; k < 128; k++)
            acc += p[k] * Wf[k * OUTC + t];
        out[g * OUTC + t] = acc;
    }
}

// ---------------- launch ----------------
extern "C" void kernel_launch(void* const* d_in, const int* in_sizes, int n_in,
                              void* d_out, int out_size) {
    const float* x     = (const float*)d_in[0];
    const float* top   = (const float*)d_in[1];
    const int*   ei    = (const int*)d_in[2];
    const int*   batch = (const int*)d_in[3];
    const float* W0    = (const float*)d_in[4];
    const float* b0    = (const float*)d_in[5];
    const float* Wg0   = (const float*)d_in[6];
    const float* W1    = (const float*)d_in[7];
    const float* b1    = (const float*)d_in[8];
    const float* Wg1   = (const float*)d_in[9];
    const float* Wf    = (const float*)d_in[10];
    const float* bf    = (const float*)d_in[11];
    float*       out   = (float*)d_out;

    cudaFuncSetAttribute(k_gemm_mma, cudaFuncAttributeMaxDynamicSharedMemorySize, SMEM_MM);

    const __nv_bfloat16* xbf; const __nv_bfloat16* hbf;
    cudaGetSymbolAddress((void**)&xbf, g_xbf);
    cudaGetSymbolAddress((void**)&hbf, g_hbf);

    const int gemmGrid = (Nn + 127) / 128;   // 391

    k_nop<<<1, 32>>>();                                                     // 0 (aligns ncu -s 5 on gemm0)
    k_init<<<(Nn * 32 + 255) / 256, 256>>>(x, W0, W1, top, Wg0, Wg1, ei);   // 1
    k_scan<<<98, 512>>>();                                                  // 2
    k_fill<<<(Ee + 255) / 256, 256>>>(ei);                                  // 3
    k_agg<<<3125, 256>>>(xbf);                                              // 4
    k_gemm_mma<<<gemmGrid, 512, SMEM_MM>>>(b0, batch, 0);                   // 5 (profiled)
    k_agg<<<3125, 256>>>(hbf);                                              // 6
    k_gemm_mma<<<gemmGrid, 512, SMEM_MM>>>(b1, batch, 1);                   // 7
    k_final<<<NG + 196, 256>>>(Wf, bf, out);                                // 8
}

// round 14
// speedup vs baseline: 1.7039x; 1.0089x over previous
#include <cuda_runtime.h>
#include <cuda_bf16.h>
#include <cstdint>

#define Nn   50000
#define Ee   800000
#define HID  128
#define OUTC 64
#define NG   64
#define TEMP_INV (1.0f/101.0f)

// ---------------- scratch (all zero at load; k_final tail restores zeros) ----------------
static __device__ int    g_deg[Nn];
static __device__ float  g_dinv[Nn];
static __device__ int    g_rowptr[Nn + 1];
static __device__ int    g_rank[Ee];                // per-edge in-node slot (from init hist)
static __device__ __align__(8) int2 g_edge[Ee];     // (src row byte-offset (bf16 row=256B), dinv bits)
static __device__ float  g_gate0[Nn * 3];
static __device__ float  g_gate1[Nn * 3];
static __device__ float  g_bufA[Nn * HID];          // agg output (fp32)
static __device__ float  g_sums[NG * HID];
static __device__ float  g_cnt[NG];
static __device__ int    g_scanFlag[128];
static __device__ int    g_scanAgg[128];
// bf16 node-feature buffers for the gather phase
static __device__ __align__(16) __nv_bfloat16 g_xbf[Nn * HID];
static __device__ __align__(16) __nv_bfloat16 g_hbf[Nn * HID];
// bf16 split transposed weights: [L][e][n][k], hi and lo
static __device__ __align__(16) __nv_bfloat16 g_Wh[2 * 3 * 128 * 128];
static __device__ __align__(16) __nv_bfloat16 g_Wl[2 * 3 * 128 * 128];

__device__ __forceinline__ uint32_t smem_u32(const void* p) {
    uint32_t a;
    asm("{ .reg .u64 t; cvta.to.shared.u64 t, %1; cvt.u32.u64 %0, t; }" : "=r"(a) : "l"(p));
    return a;
}

// ---------------- fused init: x->bf16 + weight split + gates + degree hist (rank capture) ----------------
__global__ void k_init(const float* __restrict__ x,
                       const float* __restrict__ W0, const float* __restrict__ W1,
                       const float* __restrict__ top,
                       const float* __restrict__ Wg0, const float* __restrict__ Wg1,
                       const int* __restrict__ ei) {
    int i = blockIdx.x * blockDim.x + threadIdx.x;
    if (i < Nn * 32) {
        float4 v = ((const float4*)x)[i];
        __nv_bfloat16 b[4] = {__float2bfloat16_rn(v.x), __float2bfloat16_rn(v.y),
                              __float2bfloat16_rn(v.z), __float2bfloat16_rn(v.w)};
        *(uint2*)&g_xbf[i * 4] = *(uint2*)b;
    }
    if (i < 2 * 3 * 16384) {
        int L = i / 49152, rem = i % 49152;
        int e = rem / 16384, nk = rem % 16384;
        int n = nk >> 7, k = nk & 127;
        const float* W = L ? W1 : W0;
        float w = W[e * 16384 + k * 128 + n];
        __nv_bfloat16 hi = __float2bfloat16_rn(w);
        g_Wh[i] = hi;
        g_Wl[i] = __float2bfloat16_rn(w - __bfloat162float(hi));
    }
    if (i < Ee) g_rank[i] = atomicAdd(&g_deg[ei[Ee + i]], 1);   // unique in-node slot
    if (i < Nn) {
        float t0 = top[i*4+0], t1 = top[i*4+1], t2 = top[i*4+2], t3 = top[i*4+3];
        #pragma unroll
        for (int L = 0; L < 2; L++) {
            const float* Wg = L ? Wg1 : Wg0;
            float* gate = L ? g_gate1 : g_gate0;
            float l[3];
            #pragma unroll
            for (int e = 0; e < 3; e++)
                l[e] = (t0*Wg[e*4+0] + t1*Wg[e*4+1] + t2*Wg[e*4+2] + t3*Wg[e*4+3]) * TEMP_INV;
            float mx = fmaxf(l[0], fmaxf(l[1], l[2]));
            float e0 = expf(l[0]-mx), e1 = expf(l[1]-mx), e2 = expf(l[2]-mx);
            float inv = 1.0f / (e0 + e1 + e2);
            gate[i*3+0] = e0*inv; gate[i*3+1] = e1*inv; gate[i*3+2] = e2*inv;
        }
    }
}

// ---------------- single-kernel scan (decoupled lookback) + dinv ----------------
__global__ void __launch_bounds__(512) k_scan() {
    int b = blockIdx.x, t = threadIdx.x;
    int i = b * 512 + t;
    int v = (i < Nn) ? g_deg[i] : 0;
    int lane = t & 31, w = t >> 5;
    int x = v;
    #pragma unroll
    for (int d = 1; d < 32; d <<= 1) {
        int y = __shfl_up_sync(0xFFFFFFFFu, x, d);
        if (lane >= d) x += y;
    }
    __shared__ int wsum[16];
    __shared__ int pref;
    if (lane == 31) wsum[w] = x;
    __syncthreads();
    if (w == 0) {
        int s = (lane < 16) ? wsum[lane] : 0;
        #pragma unroll
        for (int d = 1; d < 16; d <<= 1) {
            int y = __shfl_up_sync(0xFFFFFFFFu, s, d);
            if (lane >= d) s += y;
        }
        if (lane < 16) wsum[lane] = s;
        if (lane == 15) {
            atomicExch(&g_scanAgg[b], s);
            __threadfence();
            atomicExch(&g_scanFlag[b], 1);
        }
    }
    __syncthreads();
    int incl = x + (w ? wsum[w - 1] : 0);
    if (w == 0) {
        int sum = 0;
        for (int base = b - 1; base >= 0; base -= 32) {
            int j = base - lane;
            int a = 0;
            if (j >= 0) {
                while (atomicAdd(&g_scanFlag[j], 0) == 0) { }
                a = atomicAdd(&g_scanAgg[j], 0);
            }
            #pragma unroll
            for (int d = 16; d; d >>= 1) a += __shfl_down_sync(0xFFFFFFFFu, a, d);
            sum += __shfl_sync(0xFFFFFFFFu, a, 0);
        }
        if (lane == 0) pref = sum;
    }
    __syncthreads();
    if (i < Nn) {
        g_rowptr[i + 1] = incl + pref;
        g_dinv[i] = rsqrtf((float)(v + 1));
    }
    if (i == 0) g_rowptr[0] = 0;
}

// ---------------- atomic-free CSR fill via precomputed ranks ----------------
__global__ void k_fill(const int* __restrict__ ei) {
    int i = blockIdx.x * blockDim.x + threadIdx.x;
    if (i >= Ee) return;
    int s = ei[i], d = ei[Ee + i];
    int p = __ldg(&g_rowptr[d]) + g_rank[i];
    g_edge[p] = make_int2(s * 256, __float_as_int(g_dinv[s]));   // byte offset of bf16 row
}

// ---------------- CSR aggregation (bf16 gather, 2 nodes/warp) — R10-proven ----------------
__global__ void __launch_bounds__(256) k_agg(const __nv_bfloat16* __restrict__ hsrc) {
    int gw = (blockIdx.x * 256 + threadIdx.x) >> 5;   // warp id, < 25000
    int lane = threadIdx.x & 31;
    int half = lane >> 4, l16 = lane & 15;
    int node = gw * 2 + half;                          // < 50000 always
    float dd = g_dinv[node];
    const char* base = (const char*)hsrc + l16 * 16;   // this lane's 16B slice

    uint4 sv = *(const uint4*)(base + node * 256);
    float acc[8];
    {
        float2 c0 = __bfloat1622float2(*(__nv_bfloat162*)&sv.x);
        float2 c1 = __bfloat1622float2(*(__nv_bfloat162*)&sv.y);
        float2 c2 = __bfloat1622float2(*(__nv_bfloat162*)&sv.z);
        float2 c3 = __bfloat1622float2(*(__nv_bfloat162*)&sv.w);
        float s2 = dd * dd;
        acc[0]=c0.x*s2; acc[1]=c0.y*s2; acc[2]=c1.x*s2; acc[3]=c1.y*s2;
        acc[4]=c2.x*s2; acc[5]=c2.y*s2; acc[6]=c3.x*s2; acc[7]=c3.y*s2;
    }
    int j0 = g_rowptr[node], j1 = g_rowptr[node + 1];
    #pragma unroll 2
    for (int j = j0; j < j1; j++) {
        int2 ed = __ldg(&g_edge[j]);
        float wt = dd * __int_as_float(ed.y);
        uint4 u = __ldg((const uint4*)(base + ed.x));
        float2 c0 = __bfloat1622float2(*(__nv_bfloat162*)&u.x);
        float2 c1 = __bfloat1622float2(*(__nv_bfloat162*)&u.y);
        float2 c2 = __bfloat1622float2(*(__nv_bfloat162*)&u.z);
        float2 c3 = __bfloat1622float2(*(__nv_bfloat162*)&u.w);
        acc[0]+=wt*c0.x; acc[1]+=wt*c0.y; acc[2]+=wt*c1.x; acc[3]+=wt*c1.y;
        acc[4]+=wt*c2.x; acc[5]+=wt*c2.y; acc[6]+=wt*c3.x; acc[7]+=wt*c3.y;
    }
    float4* o = (float4*)&g_bufA[node * 128 + l16 * 8];
    o[0] = make_float4(acc[0], acc[1], acc[2], acc[3]);
    o[1] = make_float4(acc[4], acc[5], acc[6], acc[7]);
}

// ---------------- mma.sync bf16-split fused MoE GEMM (cp.async, scalar-LDS R10) ----------------
#define SMA_HI  0
#define SMA_LO  32768
#define SMB0    65536
#define SMB1    131072
#define SM_BIAS 196608
#define SM_GATE (196608 + 1536)
#define SM_BAT  (196608 + 3072)
#define SMEM_MM (196608 + 3072 + 512)
#define SM_STG  SMB0

#define AOFF(row, k) ((row) * 256 + (((((k) >> 3) ^ ((row) & 7))) << 4) + (((k) & 7) << 1))

__device__ __forceinline__ void mma_bf16(float* c, const uint32_t* a, const uint32_t* b) {
    asm volatile("mma.sync.aligned.m16n8k16.row.col.f32.bf16.bf16.f32 "
        "{%0,%1,%2,%3}, {%4,%5,%6,%7}, {%8,%9}, {%0,%1,%2,%3};"
        : "+f"(c[0]), "+f"(c[1]), "+f"(c[2]), "+f"(c[3])
        : "r"(a[0]), "r"(a[1]), "r"(a[2]), "r"(a[3]), "r"(b[0]), "r"(b[1]));
}

__device__ __forceinline__ void cp16(uint32_t dst, const void* src) {
    asm volatile("cp.async.cg.shared.global [%0], [%1], 16;" :: "r"(dst), "l"(src));
}

__device__ __forceinline__ void issueB(uint32_t smb, int stagebase,
                                       int layer, int e, int tid) {
    const uint4* bh = (const uint4*)(g_Wh + (layer * 3 + e) * 16384);
    const uint4* bl = (const uint4*)(g_Wl + (layer * 3 + e) * 16384);
    #pragma unroll
    for (int it = 0; it < 4; it++) {
        int idx = it * 512 + tid;
        int n = idx >> 4, kc = idx & 15;
        int off = n * 256 + ((kc ^ (n & 7)) << 4);
        cp16(smb + stagebase + off,         bh + idx);
        cp16(smb + stagebase + 32768 + off, bl + idx);
    }
    asm volatile("cp.async.commit_group;");
}

__global__ void __launch_bounds__(512) k_gemm_mma(const float* __restrict__ bias3,
                                                  const int* __restrict__ batch,
                                                  int layer) {
    extern __shared__ __align__(16) char smc[];
    const uint32_t smb = smem_u32(smc);
    const int tid = threadIdx.x;
    const int baseM = blockIdx.x * 128;
    const float* gate = layer ? g_gate1 : g_gate0;
    float* bias_s = (float*)(smc + SM_BIAS);
    float* gate_s = (float*)(smc + SM_GATE);
    int*   bat_s  = (int*)(smc + SM_BAT);

    issueB(smb, SMB0, layer, 0, tid);

    if (tid < 384) {
        bias_s[tid] = bias3[tid];
        int gi = baseM * 3 + tid;
        gate_s[tid] = (gi < Nn * 3) ? gate[gi] : 0.f;
    }
    if (layer && tid >= 384 && tid < 512) {
        int r = tid - 384;
        int nn = baseM + r;
        bat_s[r] = (nn < Nn) ? batch[nn] : -1;
    }

    // ---- build A tile (bf16 hi/lo, swizzled) from fp32 bufA ----
    #pragma unroll
    for (int it = 0; it < 4; it++) {
        int idx = it * 512 + tid;
        int row = idx >> 4, kc = idx & 15;
        int grow = baseM + row;
        float4 v0 = make_float4(0.f,0.f,0.f,0.f), v1 = v0;
        if (grow < Nn) {
            const float4* p = (const float4*)(g_bufA + grow * 128 + kc * 8);
            v0 = p[0]; v1 = p[1];
        }
        float f[8] = {v0.x, v0.y, v0.z, v0.w, v1.x, v1.y, v1.z, v1.w};
        __nv_bfloat16 h[8], l[8];
        #pragma unroll
        for (int j = 0; j < 8; j++) {
            h[j] = __float2bfloat16_rn(f[j]);
            l[j] = __float2bfloat16_rn(f[j] - __bfloat162float(h[j]));
        }
        int off = row * 256 + ((kc ^ (row & 7)) << 4);
        *(uint4*)(smc + SMA_HI + off) = *(uint4*)h;
        *(uint4*)(smc + SMA_LO + off) = *(uint4*)l;
    }

    const int lane = tid & 31, wid = tid >> 5;
    const int warpM = wid >> 2, warpN = wid & 3;
    const int g = lane >> 2, t4 = lane & 3;

    float out[2][4][4];
    #pragma unroll
    for (int mt = 0; mt < 2; mt++)
        #pragma unroll
        for (int nt = 0; nt < 4; nt++)
            #pragma unroll
            for (int j = 0; j < 4; j++) out[mt][nt][j] = 0.f;

    #pragma unroll 1
    for (int e = 0; e < 3; e++) {
        __syncthreads();
        if (e < 2) issueB(smb, (e & 1) ? SMB0 : SMB1, layer, e + 1, tid);
        if (e < 2) { asm volatile("cp.async.wait_group 1;"); }
        else       { asm volatile("cp.async.wait_group 0;"); }
        __syncthreads();

        const int sb  = (e & 1) ? SMB1 : SMB0;
        const int sbl = sb + 32768;

        float acc[2][4][4];
        #pragma unroll
        for (int mt = 0; mt < 2; mt++)
            #pragma unroll
            for (int nt = 0; nt < 4; nt++)
                #pragma unroll
                for (int j = 0; j < 4; j++) acc[mt][nt][j] = 0.f;

        #pragma unroll
        for (int ks = 0; ks < 8; ks++) {
            const int c0 = ks * 16 + t4 * 2;
            uint32_t afh[2][4], afl[2][4], bfh[4][2], bfl[4][2];
            #pragma unroll
            for (int mt = 0; mt < 2; mt++) {
                int r0 = warpM * 32 + mt * 16 + g;
                afh[mt][0] = *(const uint32_t*)(smc + SMA_HI + AOFF(r0,     c0));
                afh[mt][1] = *(const uint32_t*)(smc + SMA_HI + AOFF(r0 + 8, c0));
                afh[mt][2] = *(const uint32_t*)(smc + SMA_HI + AOFF(r0,     c0 + 8));
                afh[mt][3] = *(const uint32_t*)(smc + SMA_HI + AOFF(r0 + 8, c0 + 8));
                afl[mt][0] = *(const uint32_t*)(smc + SMA_LO + AOFF(r0,     c0));
                afl[mt][1] = *(const uint32_t*)(smc + SMA_LO + AOFF(r0 + 8, c0));
                afl[mt][2] = *(const uint32_t*)(smc + SMA_LO + AOFF(r0,     c0 + 8));
                afl[mt][3] = *(const uint32_t*)(smc + SMA_LO + AOFF(r0 + 8, c0 + 8));
            }
            #pragma unroll
            for (int nt = 0; nt < 4; nt++) {
                int n0 = warpN * 32 + nt * 8 + g;
                bfh[nt][0] = *(const uint32_t*)(smc + sb  + AOFF(n0, c0));
                bfh[nt][1] = *(const uint32_t*)(smc + sb  + AOFF(n0, c0 + 8));
                bfl[nt][0] = *(const uint32_t*)(smc + sbl + AOFF(n0, c0));
                bfl[nt][1] = *(const uint32_t*)(smc + sbl + AOFF(n0, c0 + 8));
            }
            #pragma unroll
            for (int mt = 0; mt < 2; mt++)
                #pragma unroll
                for (int nt = 0; nt < 4; nt++) {
                    mma_bf16(acc[mt][nt], afh[mt], bfh[nt]);
                    mma_bf16(acc[mt][nt], afl[mt], bfh[nt]);
                    mma_bf16(acc[mt][nt], afh[mt], bfl[nt]);
                }
        }

        #pragma unroll
        for (int mt = 0; mt < 2; mt++) {
            int rloc = warpM * 32 + mt * 16 + g;
            float g0 = gate_s[rloc * 3 + e];
            float g1 = gate_s[(rloc + 8) * 3 + e];
            #pragma unroll
            for (int nt = 0; nt < 4; nt++) {
                int col = warpN * 32 + nt * 8 + t4 * 2;
                float bb0 = bias_s[e * 128 + col], bb1 = bias_s[e * 128 + col + 1];
                out[mt][nt][0] += g0 * fmaxf(acc[mt][nt][0] + bb0, 0.f);
                out[mt][nt][1] += g0 * fmaxf(acc[mt][nt][1] + bb1, 0.f);
                out[mt][nt][2] += g1 * fmaxf(acc[mt][nt][2] + bb0, 0.f);
                out[mt][nt][3] += g1 * fmaxf(acc[mt][nt][3] + bb1, 0.f);
            }
        }
    }

    if (!layer) {
        // ---- layer 0: write h as bf16 for the next gather ----
        #pragma unroll
        for (int mt = 0; mt < 2; mt++) {
            int r0 = baseM + warpM * 32 + mt * 16 + g;
            #pragma unroll
            for (int nt = 0; nt < 4; nt++) {
                int col = warpN * 32 + nt * 8 + t4 * 2;
                __nv_bfloat16 p0[2] = {__float2bfloat16_rn(out[mt][nt][0]),
                                       __float2bfloat16_rn(out[mt][nt][1])};
                __nv_bfloat16 p1[2] = {__float2bfloat16_rn(out[mt][nt][2]),
                                       __float2bfloat16_rn(out[mt][nt][3])};
                if (r0 < Nn)     *(uint32_t*)&g_hbf[r0 * 128 + col]       = *(uint32_t*)p0;
                if (r0 + 8 < Nn) *(uint32_t*)&g_hbf[(r0 + 8) * 128 + col] = *(uint32_t*)p1;
            }
        }
    } else {
        // ---- layer 1: fused pooling via smem staging + segment scan ----
        __syncthreads();
        float* stg = (float*)(smc + SM_STG);
        #pragma unroll
        for (int mt = 0; mt < 2; mt++) {
            int rloc = warpM * 32 + mt * 16 + g;
            #pragma unroll
            for (int nt = 0; nt < 4; nt++) {
                int col = warpN * 32 + nt * 8 + t4 * 2;
                stg[rloc * 132 + col]           = out[mt][nt][0];
                stg[rloc * 132 + col + 1]       = out[mt][nt][1];
                stg[(rloc + 8) * 132 + col]     = out[mt][nt][2];
                stg[(rloc + 8) * 132 + col + 1] = out[mt][nt][3];
            }
        }
        __syncthreads();
        int col = tid & 127, grp = tid >> 7;
        int rbeg = grp * 32;
        int cur = -2; float acc = 0.f; float cnt = 0.f;
        #pragma unroll 4
        for (int r = rbeg; r < rbeg + 32; r++) {
            int b = bat_s[r];
            if (b != cur) {
                if (cur >= 0) {
                    atomicAdd(&g_sums[cur * 128 + col], acc);
                    if (col == 0) atomicAdd(&g_cnt[cur], cnt);
                }
                cur = b; acc = 0.f; cnt = 0.f;
            }
            if (b >= 0) { acc += stg[r * 132 + col]; cnt += 1.f; }
        }
        if (cur >= 0) {
            atomicAdd(&g_sums[cur * 128 + col], acc);
            if (col == 0) atomicAdd(&g_cnt[cur], cnt);
        }
    }
}

// ---------------- final linear + scratch cleanup (restores zero invariant) ----------------
__global__ void __launch_bounds__(256) k_final(const float* __restrict__ Wf,
                                               const float* __restrict__ bf,
                                               float* __restrict__ out) {
    int t = threadIdx.x;
    if (blockIdx.x >= NG) {
        int idx = (blockIdx.x - NG) * 256 + t;
        if (idx < Nn) g_deg[idx] = 0;
        if (idx < 128) g_scanFlag[idx] = 0;
        return;
    }
    __shared__ float p[128];
    int g = blockIdx.x;
    float inv = 1.0f / fmaxf(g_cnt[g], 1.0f);
    if (t < 128) { p[t] = g_sums[g * 128 + t] * inv; g_sums[g * 128 + t] = 0.f; }
    __syncthreads();
    if (t == 0) g_cnt[g] = 0.f;
    if (t < OUTC) {
        float acc = bf[t];
        #pragma unroll 16
        for (int k = 0; k < 128; k++)
            acc += p[k] * Wf[k * OUTC + t];
        out[g * OUTC + t] = acc;
    }
}

// ---------------- launch ----------------
extern "C" void kernel_launch(void* const* d_in, const int* in_sizes, int n_in,
                              void* d_out, int out_size) {
    const float* x     = (const float*)d_in[0];
    const float* top   = (const float*)d_in[1];
    const int*   ei    = (const int*)d_in[2];
    const int*   batch = (const int*)d_in[3];
    const float* W0    = (const float*)d_in[4];
    const float* b0    = (const float*)d_in[5];
    const float* Wg0   = (const float*)d_in[6];
    const float* W1    = (const float*)d_in[7];
    const float* b1    = (const float*)d_in[8];
    const float* Wg1   = (const float*)d_in[9];
    const float* Wf    = (const float*)d_in[10];
    const float* bf    = (const float*)d_in[11];
    float*       out   = (float*)d_out;

    cudaFuncSetAttribute(k_gemm_mma, cudaFuncAttributeMaxDynamicSharedMemorySize, SMEM_MM);

    const __nv_bfloat16* xbf; const __nv_bfloat16* hbf;
    cudaGetSymbolAddress((void**)&xbf, g_xbf);
    cudaGetSymbolAddress((void**)&hbf, g_hbf);

    const int gemmGrid = (Nn + 127) / 128;   // 391

    k_init<<<(Nn * 32 + 255) / 256, 256>>>(x, W0, W1, top, Wg0, Wg1, ei);   // 0
    k_scan<<<98, 512>>>();                                                  // 1
    k_fill<<<(Ee + 255) / 256, 256>>>(ei);                                  // 2
    k_agg<<<3125, 256>>>(xbf);                                              // 3
    k_gemm_mma<<<gemmGrid, 512, SMEM_MM>>>(b0, batch, 0);                   // 4
    k_agg<<<3125, 256>>>(hbf);                                              // 5
    k_gemm_mma<<<gemmGrid, 512, SMEM_MM>>>(b1, batch, 1);                   // 6
    k_final<<<NG + 196, 256>>>(Wf, bf, out);                                // 7
}

// round 15
// speedup vs baseline: 1.9258x; 1.1302x over previous
#include <cuda_runtime.h>
#include <cuda_bf16.h>
#include <cstdint>

#define Nn   50000
#define Ee   800000
#define HID  128
#define OUTC 64
#define NG   64
#define TEMP_INV (1.0f/101.0f)

// ---------------- scratch (all zero at load; k_final tail restores zeros) ----------------
static __device__ int    g_deg[Nn];
static __device__ float  g_dinv[Nn];
static __device__ int    g_rowptr[Nn + 1];
static __device__ int    g_rank[Ee];                // per-edge in-node slot (from init hist)
static __device__ __align__(8) int2 g_edge[Ee];     // (src row byte-offset (bf16 row=256B), dinv bits)
static __device__ float  g_gate0[Nn * 3];
static __device__ float  g_gate1[Nn * 3];
static __device__ float  g_bufA[Nn * HID];          // agg output (fp32)
static __device__ float  g_sums[NG * HID];
static __device__ float  g_cnt[NG];
static __device__ int    g_scanFlag[128];
static __device__ int    g_scanAgg[128];
// bf16 node-feature buffers for the gather phase
static __device__ __align__(16) __nv_bfloat16 g_xbf[Nn * HID];
static __device__ __align__(16) __nv_bfloat16 g_hbf[Nn * HID];
// bf16 split transposed weights: [L][e][n][k], hi and lo
static __device__ __align__(16) __nv_bfloat16 g_Wh[2 * 3 * 128 * 128];
static __device__ __align__(16) __nv_bfloat16 g_Wl[2 * 3 * 128 * 128];

__device__ __forceinline__ uint32_t smem_u32(const void* p) {
    uint32_t a;
    asm("{ .reg .u64 t; cvta.to.shared.u64 t, %1; cvt.u32.u64 %0, t; }" : "=r"(a) : "l"(p));
    return a;
}

// ---------------- fused init: x->bf16 + weight split + gates + degree hist (rank capture) ----------------
__global__ void k_init(const float* __restrict__ x,
                       const float* __restrict__ W0, const float* __restrict__ W1,
                       const float* __restrict__ top,
                       const float* __restrict__ Wg0, const float* __restrict__ Wg1,
                       const int* __restrict__ ei) {
    int i = blockIdx.x * blockDim.x + threadIdx.x;
    if (i < Nn * 32) {
        float4 v = ((const float4*)x)[i];
        __nv_bfloat16 b[4] = {__float2bfloat16_rn(v.x), __float2bfloat16_rn(v.y),
                              __float2bfloat16_rn(v.z), __float2bfloat16_rn(v.w)};
        *(uint2*)&g_xbf[i * 4] = *(uint2*)b;
    }
    if (i < 2 * 3 * 16384) {
        int q = i >> 14;            // 0..5
        int L = (q >= 3) ? 1 : 0;
        int e = q - 3 * L;
        int nk = i & 16383;
        int n = nk >> 7, k = nk & 127;
        const float* W = L ? W1 : W0;
        float w = W[e * 16384 + k * 128 + n];
        __nv_bfloat16 hi = __float2bfloat16_rn(w);
        g_Wh[i] = hi;
        g_Wl[i] = __float2bfloat16_rn(w - __bfloat162float(hi));
    }
    if (i < Ee) g_rank[i] = atomicAdd(&g_deg[ei[Ee + i]], 1);   // unique in-node slot
    if (i < Nn) {
        float t0 = top[i*4+0], t1 = top[i*4+1], t2 = top[i*4+2], t3 = top[i*4+3];
        #pragma unroll
        for (int L = 0; L < 2; L++) {
            const float* Wg = L ? Wg1 : Wg0;
            float* gate = L ? g_gate1 : g_gate0;
            float l[3];
            #pragma unroll
            for (int e = 0; e < 3; e++)
                l[e] = (t0*Wg[e*4+0] + t1*Wg[e*4+1] + t2*Wg[e*4+2] + t3*Wg[e*4+3]) * TEMP_INV;
            float mx = fmaxf(l[0], fmaxf(l[1], l[2]));
            float e0 = expf(l[0]-mx), e1 = expf(l[1]-mx), e2 = expf(l[2]-mx);
            float inv = 1.0f / (e0 + e1 + e2);
            gate[i*3+0] = e0*inv; gate[i*3+1] = e1*inv; gate[i*3+2] = e2*inv;
        }
    }
}

// ---------------- single-kernel scan (decoupled lookback) + dinv ----------------
__global__ void __launch_bounds__(512) k_scan() {
    int b = blockIdx.x, t = threadIdx.x;
    int i = b * 512 + t;
    int v = (i < Nn) ? g_deg[i] : 0;
    int lane = t & 31, w = t >> 5;
    int x = v;
    #pragma unroll
    for (int d = 1; d < 32; d <<= 1) {
        int y = __shfl_up_sync(0xFFFFFFFFu, x, d);
        if (lane >= d) x += y;
    }
    __shared__ int wsum[16];
    __shared__ int pref;
    if (lane == 31) wsum[w] = x;
    __syncthreads();
    if (w == 0) {
        int s = (lane < 16) ? wsum[lane] : 0;
        #pragma unroll
        for (int d = 1; d < 16; d <<= 1) {
            int y = __shfl_up_sync(0xFFFFFFFFu, s, d);
            if (lane >= d) s += y;
        }
        if (lane < 16) wsum[lane] = s;
        if (lane == 15) {
            atomicExch(&g_scanAgg[b], s);
            __threadfence();
            atomicExch(&g_scanFlag[b], 1);
        }
    }
    __syncthreads();
    int incl = x + (w ? wsum[w - 1] : 0);
    if (w == 0) {
        int sum = 0;
        for (int base = b - 1; base >= 0; base -= 32) {
            int j = base - lane;
            int a = 0;
            if (j >= 0) {
                while (atomicAdd(&g_scanFlag[j], 0) == 0) { }
                a = atomicAdd(&g_scanAgg[j], 0);
            }
            #pragma unroll
            for (int d = 16; d; d >>= 1) a += __shfl_down_sync(0xFFFFFFFFu, a, d);
            sum += __shfl_sync(0xFFFFFFFFu, a, 0);
        }
        if (lane == 0) pref = sum;
    }
    __syncthreads();
    if (i < Nn) {
        g_rowptr[i + 1] = incl + pref;
        g_dinv[i] = rsqrtf((float)(v + 1));
    }
    if (i == 0) g_rowptr[0] = 0;
}

// ---------------- atomic-free CSR fill via precomputed ranks ----------------
__global__ void k_fill(const int* __restrict__ ei) {
    int i = blockIdx.x * blockDim.x + threadIdx.x;
    if (i >= Ee) return;
    int s = ei[i], d = ei[Ee + i];
    int p = __ldg(&g_rowptr[d]) + g_rank[i];
    g_edge[p] = make_int2(s * 256, __float_as_int(g_dinv[s]));   // byte offset of bf16 row
}

// ---------------- CSR aggregation (bf16 gather, 2 nodes/warp, dd factored) ----------------
__global__ void __launch_bounds__(256) k_agg(const __nv_bfloat16* __restrict__ hsrc) {
    int gw = (blockIdx.x * 256 + threadIdx.x) >> 5;   // warp id, < 25000
    int lane = threadIdx.x & 31;
    int half = lane >> 4, l16 = lane & 15;
    int node = gw * 2 + half;                          // < 50000 always
    float dd = g_dinv[node];
    const char* base = (const char*)hsrc + l16 * 16;   // this lane's 16B slice

    uint4 sv = *(const uint4*)(base + node * 256);
    float acc[8];
    {
        float2 c0 = __bfloat1622float2(*(__nv_bfloat162*)&sv.x);
        float2 c1 = __bfloat1622float2(*(__nv_bfloat162*)&sv.y);
        float2 c2 = __bfloat1622float2(*(__nv_bfloat162*)&sv.z);
        float2 c3 = __bfloat1622float2(*(__nv_bfloat162*)&sv.w);
        // self-loop contributes dd*v inside the dd-factored sum (result scaled by dd at end)
        acc[0]=c0.x*dd; acc[1]=c0.y*dd; acc[2]=c1.x*dd; acc[3]=c1.y*dd;
        acc[4]=c2.x*dd; acc[5]=c2.y*dd; acc[6]=c3.x*dd; acc[7]=c3.y*dd;
    }
    int j0 = g_rowptr[node], j1 = g_rowptr[node + 1];
    #pragma unroll 2
    for (int j = j0; j < j1; j++) {
        int2 ed = __ldg(&g_edge[j]);
        float wt = __int_as_float(ed.y);               // dinv[src]; dd applied at end
        uint4 u = __ldg((const uint4*)(base + ed.x));
        float2 c0 = __bfloat1622float2(*(__nv_bfloat162*)&u.x);
        float2 c1 = __bfloat1622float2(*(__nv_bfloat162*)&u.y);
        float2 c2 = __bfloat1622float2(*(__nv_bfloat162*)&u.z);
        float2 c3 = __bfloat1622float2(*(__nv_bfloat162*)&u.w);
        acc[0]+=wt*c0.x; acc[1]+=wt*c0.y; acc[2]+=wt*c1.x; acc[3]+=wt*c1.y;
        acc[4]+=wt*c2.x; acc[5]+=wt*c2.y; acc[6]+=wt*c3.x; acc[7]+=wt*c3.y;
    }
    float4* o = (float4*)&g_bufA[node * 128 + l16 * 8];
    o[0] = make_float4(acc[0]*dd, acc[1]*dd, acc[2]*dd, acc[3]*dd);
    o[1] = make_float4(acc[4]*dd, acc[5]*dd, acc[6]*dd, acc[7]*dd);
}

// ---------------- mma.sync 2-pass fused MoE GEMM: A_hi x (B_hi + B_lo) ----------------
#define SMA_HI  0
#define SMB0    32768
#define SMB1    98304
#define SM_BIAS 163840
#define SM_GATE (163840 + 1536)
#define SM_BAT  (163840 + 3072)
#define SMEM_MM (163840 + 3072 + 512)
#define SM_STG  SMB0                      // pool staging: 128*132*4 = 67584 B, fits in SMB0+SMB1

#define AOFF(row, k) ((row) * 256 + (((((k) >> 3) ^ ((row) & 7))) << 4) + (((k) & 7) << 1))

__device__ __forceinline__ void mma_bf16(float* c, const uint32_t* a, const uint32_t* b) {
    asm volatile("mma.sync.aligned.m16n8k16.row.col.f32.bf16.bf16.f32 "
        "{%0,%1,%2,%3}, {%4,%5,%6,%7}, {%8,%9}, {%0,%1,%2,%3};"
        : "+f"(c[0]), "+f"(c[1]), "+f"(c[2]), "+f"(c[3])
        : "r"(a[0]), "r"(a[1]), "r"(a[2]), "r"(a[3]), "r"(b[0]), "r"(b[1]));
}

__device__ __forceinline__ void cp16(uint32_t dst, const void* src) {
    asm volatile("cp.async.cg.shared.global [%0], [%1], 16;" :: "r"(dst), "l"(src));
}

__device__ __forceinline__ void issueB(uint32_t smb, int stagebase,
                                       int layer, int e, int tid) {
    const uint4* bh = (const uint4*)(g_Wh + (layer * 3 + e) * 16384);
    const uint4* bl = (const uint4*)(g_Wl + (layer * 3 + e) * 16384);
    #pragma unroll
    for (int it = 0; it < 4; it++) {
        int idx = it * 512 + tid;
        int n = idx >> 4, kc = idx & 15;
        int off = n * 256 + ((kc ^ (n & 7)) << 4);
        cp16(smb + stagebase + off,         bh + idx);
        cp16(smb + stagebase + 32768 + off, bl + idx);
    }
    asm volatile("cp.async.commit_group;");
}

__global__ void __launch_bounds__(512) k_gemm_mma(const float* __restrict__ bias3,
                                                  const int* __restrict__ batch,
                                                  int layer) {
    extern __shared__ __align__(16) char smc[];
    const uint32_t smb = smem_u32(smc);
    const int tid = threadIdx.x;
    const int baseM = blockIdx.x * 128;
    const float* gate = layer ? g_gate1 : g_gate0;
    float* bias_s = (float*)(smc + SM_BIAS);
    float* gate_s = (float*)(smc + SM_GATE);
    int*   bat_s  = (int*)(smc + SM_BAT);

    issueB(smb, SMB0, layer, 0, tid);

    if (tid < 384) {
        bias_s[tid] = bias3[tid];
        int gi = baseM * 3 + tid;
        gate_s[tid] = (gi < Nn * 3) ? gate[gi] : 0.f;
    }
    if (layer && tid >= 384 && tid < 512) {
        int r = tid - 384;
        int nn = baseM + r;
        bat_s[r] = (nn < Nn) ? batch[nn] : -1;
    }

    // ---- build A tile (bf16 hi only, swizzled) from fp32 bufA ----
    #pragma unroll
    for (int it = 0; it < 4; it++) {
        int idx = it * 512 + tid;
        int row = idx >> 4, kc = idx & 15;
        int grow = baseM + row;
        float4 v0 = make_float4(0.f,0.f,0.f,0.f), v1 = v0;
        if (grow < Nn) {
            const float4* p = (const float4*)(g_bufA + grow * 128 + kc * 8);
            v0 = p[0]; v1 = p[1];
        }
        float f[8] = {v0.x, v0.y, v0.z, v0.w, v1.x, v1.y, v1.z, v1.w};
        __nv_bfloat16 h[8];
        #pragma unroll
        for (int j = 0; j < 8; j++) h[j] = __float2bfloat16_rn(f[j]);
        int off = row * 256 + ((kc ^ (row & 7)) << 4);
        *(uint4*)(smc + SMA_HI + off) = *(uint4*)h;
    }

    const int lane = tid & 31, wid = tid >> 5;
    const int warpM = wid >> 2, warpN = wid & 3;
    const int g = lane >> 2, t4 = lane & 3;

    float out[2][4][4];
    #pragma unroll
    for (int mt = 0; mt < 2; mt++)
        #pragma unroll
        for (int nt = 0; nt < 4; nt++)
            #pragma unroll
            for (int j = 0; j < 4; j++) out[mt][nt][j] = 0.f;

    #pragma unroll 1
    for (int e = 0; e < 3; e++) {
        __syncthreads();
        if (e < 2) issueB(smb, (e & 1) ? SMB0 : SMB1, layer, e + 1, tid);
        if (e < 2) { asm volatile("cp.async.wait_group 1;"); }
        else       { asm volatile("cp.async.wait_group 0;"); }
        __syncthreads();

        const int sb  = (e & 1) ? SMB1 : SMB0;
        const int sbl = sb + 32768;

        float acc[2][4][4];
        #pragma unroll
        for (int mt = 0; mt < 2; mt++)
            #pragma unroll
            for (int nt = 0; nt < 4; nt++)
                #pragma unroll
                for (int j = 0; j < 4; j++) acc[mt][nt][j] = 0.f;

        #pragma unroll
        for (int ks = 0; ks < 8; ks++) {
            const int c0 = ks * 16 + t4 * 2;
            uint32_t afh[2][4], bfh[4][2], bfl[4][2];
            #pragma unroll
            for (int mt = 0; mt < 2; mt++) {
                int r0 = warpM * 32 + mt * 16 + g;
                afh[mt][0] = *(const uint32_t*)(smc + SMA_HI + AOFF(r0,     c0));
                afh[mt][1] = *(const uint32_t*)(smc + SMA_HI + AOFF(r0 + 8, c0));
                afh[mt][2] = *(const uint32_t*)(smc + SMA_HI + AOFF(r0,     c0 + 8));
                afh[mt][3] = *(const uint32_t*)(smc + SMA_HI + AOFF(r0 + 8, c0 + 8));
            }
            #pragma unroll
            for (int nt = 0; nt < 4; nt++) {
                int n0 = warpN * 32 + nt * 8 + g;
                bfh[nt][0] = *(const uint32_t*)(smc + sb  + AOFF(n0, c0));
                bfh[nt][1] = *(const uint32_t*)(smc + sb  + AOFF(n0, c0 + 8));
                bfl[nt][0] = *(const uint32_t*)(smc + sbl + AOFF(n0, c0));
                bfl[nt][1] = *(const uint32_t*)(smc + sbl + AOFF(n0, c0 + 8));
            }
            #pragma unroll
            for (int mt = 0; mt < 2; mt++)
                #pragma unroll
                for (int nt = 0; nt < 4; nt++) {
                    mma_bf16(acc[mt][nt], afh[mt], bfh[nt]);
                    mma_bf16(acc[mt][nt], afh[mt], bfl[nt]);
                }
        }

        #pragma unroll
        for (int mt = 0; mt < 2; mt++) {
            int rloc = warpM * 32 + mt * 16 + g;
            float g0 = gate_s[rloc * 3 + e];
            float g1 = gate_s[(rloc + 8) * 3 + e];
            #pragma unroll
            for (int nt = 0; nt < 4; nt++) {
                int col = warpN * 32 + nt * 8 + t4 * 2;
                float bb0 = bias_s[e * 128 + col], bb1 = bias_s[e * 128 + col + 1];
                out[mt][nt][0] += g0 * fmaxf(acc[mt][nt][0] + bb0, 0.f);
                out[mt][nt][1] += g0 * fmaxf(acc[mt][nt][1] + bb1, 0.f);
                out[mt][nt][2] += g1 * fmaxf(acc[mt][nt][2] + bb0, 0.f);
                out[mt][nt][3] += g1 * fmaxf(acc[mt][nt][3] + bb1, 0.f);
            }
        }
    }

    if (!layer) {
        // ---- layer 0: write h as bf16 for the next gather ----
        #pragma unroll
        for (int mt = 0; mt < 2; mt++) {
            int r0 = baseM + warpM * 32 + mt * 16 + g;
            #pragma unroll
            for (int nt = 0; nt < 4; nt++) {
                int col = warpN * 32 + nt * 8 + t4 * 2;
                __nv_bfloat16 p0[2] = {__float2bfloat16_rn(out[mt][nt][0]),
                                       __float2bfloat16_rn(out[mt][nt][1])};
                __nv_bfloat16 p1[2] = {__float2bfloat16_rn(out[mt][nt][2]),
                                       __float2bfloat16_rn(out[mt][nt][3])};
                if (r0 < Nn)     *(uint32_t*)&g_hbf[r0 * 128 + col]       = *(uint32_t*)p0;
                if (r0 + 8 < Nn) *(uint32_t*)&g_hbf[(r0 + 8) * 128 + col] = *(uint32_t*)p1;
            }
        }
    } else {
        // ---- layer 1: fused pooling via smem staging + segment scan ----
        __syncthreads();
        float* stg = (float*)(smc + SM_STG);
        #pragma unroll
        for (int mt = 0; mt < 2; mt++) {
            int rloc = warpM * 32 + mt * 16 + g;
            #pragma unroll
            for (int nt = 0; nt < 4; nt++) {
                int col = warpN * 32 + nt * 8 + t4 * 2;
                stg[rloc * 132 + col]           = out[mt][nt][0];
                stg[rloc * 132 + col + 1]       = out[mt][nt][1];
                stg[(rloc + 8) * 132 + col]     = out[mt][nt][2];
                stg[(rloc + 8) * 132 + col + 1] = out[mt][nt][3];
            }
        }
        __syncthreads();
        int col = tid & 127, grp = tid >> 7;
        int rbeg = grp * 32;
        int cur = -2; float acc = 0.f; float cnt = 0.f;
        #pragma unroll 4
        for (int r = rbeg; r < rbeg + 32; r++) {
            int b = bat_s[r];
            if (b != cur) {
                if (cur >= 0) {
                    atomicAdd(&g_sums[cur * 128 + col], acc);
                    if (col == 0) atomicAdd(&g_cnt[cur], cnt);
                }
                cur = b; acc = 0.f; cnt = 0.f;
            }
            if (b >= 0) { acc += stg[r * 132 + col]; cnt += 1.f; }
        }
        if (cur >= 0) {
            atomicAdd(&g_sums[cur * 128 + col], acc);
            if (col == 0) atomicAdd(&g_cnt[cur], cnt);
        }
    }
}

// ---------------- final linear + scratch cleanup (restores zero invariant) ----------------
__global__ void __launch_bounds__(256) k_final(const float* __restrict__ Wf,
                                               const float* __restrict__ bf,
                                               float* __restrict__ out) {
    int t = threadIdx.x;
    if (blockIdx.x >= NG) {
        int idx = (blockIdx.x - NG) * 256 + t;
        if (idx < Nn) g_deg[idx] = 0;
        if (idx < 128) g_scanFlag[idx] = 0;
        return;
    }
    __shared__ float p[128];
    int g = blockIdx.x;
    float inv = 1.0f / fmaxf(g_cnt[g], 1.0f);
    if (t < 128) { p[t] = g_sums[g * 128 + t] * inv; g_sums[g * 128 + t] = 0.f; }
    __syncthreads();
    if (t == 0) g_cnt[g] = 0.f;
    if (t < OUTC) {
        float acc = bf[t];
        #pragma unroll 16
        for (int k = 0; k < 128; k++)
            acc += p[k] * Wf[k * OUTC + t];
        out[g * OUTC + t] = acc;
    }
}

// ---------------- launch ----------------
extern "C" void kernel_launch(void* const* d_in, const int* in_sizes, int n_in,
                              void* d_out, int out_size) {
    const float* x     = (const float*)d_in[0];
    const float* top   = (const float*)d_in[1];
    const int*   ei    = (const int*)d_in[2];
    const int*   batch = (const int*)d_in[3];
    const float* W0    = (const float*)d_in[4];
    const float* b0    = (const float*)d_in[5];
    const float* Wg0   = (const float*)d_in[6];
    const float* W1    = (const float*)d_in[7];
    const float* b1    = (const float*)d_in[8];
    const float* Wg1   = (const float*)d_in[9];
    const float* Wf    = (const float*)d_in[10];
    const float* bf    = (const float*)d_in[11];
    float*       out   = (float*)d_out;

    cudaFuncSetAttribute(k_gemm_mma, cudaFuncAttributeMaxDynamicSharedMemorySize, SMEM_MM);

    const __nv_bfloat16* xbf; const __nv_bfloat16* hbf;
    cudaGetSymbolAddress((void**)&xbf, g_xbf);
    cudaGetSymbolAddress((void**)&hbf, g_hbf);

    const int gemmGrid = (Nn + 127) / 128;   // 391

    k_init<<<(Nn * 32 + 255) / 256, 256>>>(x, W0, W1, top, Wg0, Wg1, ei);   // 0
    k_scan<<<98, 512>>>();                                                  // 1
    k_fill<<<(Ee + 255) / 256, 256>>>(ei);                                  // 2
    k_agg<<<3125, 256>>>(xbf);                                              // 3
    k_gemm_mma<<<gemmGrid, 512, SMEM_MM>>>(b0, batch, 0);                   // 4
    k_agg<<<3125, 256>>>(hbf);                                              // 5
    k_gemm_mma<<<gemmGrid, 512, SMEM_MM>>>(b1, batch, 1);                   // 6
    k_final<<<NG + 196, 256>>>(Wf, bf, out);                                // 7
}

// round 17
// speedup vs baseline: 1.9611x; 1.0183x over previous
#include <cuda_runtime.h>
#include <cuda_bf16.h>
#include <cstdint>

#define Nn   50000
#define Ee   800000
#define HID  128
#define OUTC 64
#define NG   64
#define TEMP_INV (1.0f/101.0f)

// ---------------- scratch (all zero at load; k_final tail restores zeros) ----------------
static __device__ int    g_deg[Nn];
static __device__ float  g_dinv[Nn];
static __device__ int    g_rowptr[Nn + 1];
static __device__ int    g_rank[Ee];
static __device__ __align__(8) int2 g_edge[Ee];     // (src row byte-offset, dinv bits)
static __device__ float  g_gate0[Nn * 3];
static __device__ float  g_gate1[Nn * 3];
static __device__ float  g_bufA[Nn * HID];          // agg output (fp32)
static __device__ float  g_sums[NG * HID];
static __device__ float  g_cnt[NG];
static __device__ int    g_scanFlag[128];
static __device__ int    g_scanAgg[128];
static __device__ __align__(16) __nv_bfloat16 g_xbf[Nn * HID];
static __device__ __align__(16) __nv_bfloat16 g_hbf[Nn * HID];
static __device__ __align__(16) __nv_bfloat16 g_Wh[2 * 3 * 128 * 128];
static __device__ __align__(16) __nv_bfloat16 g_Wl[2 * 3 * 128 * 128];

__device__ __forceinline__ uint32_t smem_u32(const void* p) {
    uint32_t a;
    asm("{ .reg .u64 t; cvta.to.shared.u64 t, %1; cvt.u32.u64 %0, t; }" : "=r"(a) : "l"(p));
    return a;
}

// ---------------- fused init ----------------
__global__ void k_init(const float* __restrict__ x,
                       const float* __restrict__ W0, const float* __restrict__ W1,
                       const float* __restrict__ top,
                       const float* __restrict__ Wg0, const float* __restrict__ Wg1,
                       const int* __restrict__ ei) {
    int i = blockIdx.x * blockDim.x + threadIdx.x;
    if (i < Nn * 32) {
        float4 v = ((const float4*)x)[i];
        __nv_bfloat16 b[4] = {__float2bfloat16_rn(v.x), __float2bfloat16_rn(v.y),
                              __float2bfloat16_rn(v.z), __float2bfloat16_rn(v.w)};
        *(uint2*)&g_xbf[i * 4] = *(uint2*)b;
    }
    if (i < 2 * 3 * 16384) {
        int q = i >> 14;
        int L = (q >= 3) ? 1 : 0;
        int e = q - 3 * L;
        int nk = i & 16383;
        int n = nk >> 7, k = nk & 127;
        const float* W = L ? W1 : W0;
        float w = W[e * 16384 + k * 128 + n];
        __nv_bfloat16 hi = __float2bfloat16_rn(w);
        g_Wh[i] = hi;
        g_Wl[i] = __float2bfloat16_rn(w - __bfloat162float(hi));
    }
    if (i < Ee) g_rank[i] = atomicAdd(&g_deg[ei[Ee + i]], 1);
    if (i < Nn) {
        float t0 = top[i*4+0], t1 = top[i*4+1], t2 = top[i*4+2], t3 = top[i*4+3];
        #pragma unroll
        for (int L = 0; L < 2; L++) {
            const float* Wg = L ? Wg1 : Wg0;
            float* gate = L ? g_gate1 : g_gate0;
            float l[3];
            #pragma unroll
            for (int e = 0; e < 3; e++)
                l[e] = (t0*Wg[e*4+0] + t1*Wg[e*4+1] + t2*Wg[e*4+2] + t3*Wg[e*4+3]) * TEMP_INV;
            float mx = fmaxf(l[0], fmaxf(l[1], l[2]));
            float e0 = expf(l[0]-mx), e1 = expf(l[1]-mx), e2 = expf(l[2]-mx);
            float inv = 1.0f / (e0 + e1 + e2);
            gate[i*3+0] = e0*inv; gate[i*3+1] = e1*inv; gate[i*3+2] = e2*inv;
        }
    }
}

// ---------------- single-kernel scan (decoupled lookback) + dinv ----------------
__global__ void __launch_bounds__(512) k_scan() {
    int b = blockIdx.x, t = threadIdx.x;
    int i = b * 512 + t;
    int v = (i < Nn) ? g_deg[i] : 0;
    int lane = t & 31, w = t >> 5;
    int x = v;
    #pragma unroll
    for (int d = 1; d < 32; d <<= 1) {
        int y = __shfl_up_sync(0xFFFFFFFFu, x, d);
        if (lane >= d) x += y;
    }
    __shared__ int wsum[16];
    __shared__ int pref;
    if (lane == 31) wsum[w] = x;
    __syncthreads();
    if (w == 0) {
        int s = (lane < 16) ? wsum[lane] : 0;
        #pragma unroll
        for (int d = 1; d < 16; d <<= 1) {
            int y = __shfl_up_sync(0xFFFFFFFFu, s, d);
            if (lane >= d) s += y;
        }
        if (lane < 16) wsum[lane] = s;
        if (lane == 15) {
            atomicExch(&g_scanAgg[b], s);
            __threadfence();
            atomicExch(&g_scanFlag[b], 1);
        }
    }
    __syncthreads();
    int incl = x + (w ? wsum[w - 1] : 0);
    if (w == 0) {
        int sum = 0;
        for (int base = b - 1; base >= 0; base -= 32) {
            int j = base - lane;
            int a = 0;
            if (j >= 0) {
                while (atomicAdd(&g_scanFlag[j], 0) == 0) { }
                a = atomicAdd(&g_scanAgg[j], 0);
            }
            #pragma unroll
            for (int d = 16; d; d >>= 1) a += __shfl_down_sync(0xFFFFFFFFu, a, d);
            sum += __shfl_sync(0xFFFFFFFFu, a, 0);
        }
        if (lane == 0) pref = sum;
    }
    __syncthreads();
    if (i < Nn) {
        g_rowptr[i + 1] = incl + pref;
        g_dinv[i] = rsqrtf((float)(v + 1));
    }
    if (i == 0) g_rowptr[0] = 0;
}

// ---------------- atomic-free CSR fill ----------------
__global__ void k_fill(const int* __restrict__ ei) {
    int i = blockIdx.x * blockDim.x + threadIdx.x;
    if (i >= Ee) return;
    int s = ei[i], d = ei[Ee + i];
    int p = __ldg(&g_rowptr[d]) + g_rank[i];
    g_edge[p] = make_int2(s * 256, __float_as_int(g_dinv[s]));
}

// ---------------- CSR aggregation (bf16 gather, 2 nodes/warp, dd factored) ----------------
__global__ void __launch_bounds__(256) k_agg(const __nv_bfloat16* __restrict__ hsrc) {
    int gw = (blockIdx.x * 256 + threadIdx.x) >> 5;
    int lane = threadIdx.x & 31;
    int half = lane >> 4, l16 = lane & 15;
    int node = gw * 2 + half;
    float dd = g_dinv[node];
    const char* base = (const char*)hsrc + l16 * 16;

    uint4 sv = *(const uint4*)(base + node * 256);
    float acc[8];
    {
        float2 c0 = __bfloat1622float2(*(__nv_bfloat162*)&sv.x);
        float2 c1 = __bfloat1622float2(*(__nv_bfloat162*)&sv.y);
        float2 c2 = __bfloat1622float2(*(__nv_bfloat162*)&sv.z);
        float2 c3 = __bfloat1622float2(*(__nv_bfloat162*)&sv.w);
        acc[0]=c0.x*dd; acc[1]=c0.y*dd; acc[2]=c1.x*dd; acc[3]=c1.y*dd;
        acc[4]=c2.x*dd; acc[5]=c2.y*dd; acc[6]=c3.x*dd; acc[7]=c3.y*dd;
    }
    int j0 = g_rowptr[node], j1 = g_rowptr[node + 1];
    #pragma unroll 2
    for (int j = j0; j < j1; j++) {
        int2 ed = __ldg(&g_edge[j]);
        float wt = __int_as_float(ed.y);
        uint4 u = __ldg((const uint4*)(base + ed.x));
        float2 c0 = __bfloat1622float2(*(__nv_bfloat162*)&u.x);
        float2 c1 = __bfloat1622float2(*(__nv_bfloat162*)&u.y);
        float2 c2 = __bfloat1622float2(*(__nv_bfloat162*)&u.z);
        float2 c3 = __bfloat1622float2(*(__nv_bfloat162*)&u.w);
        acc[0]+=wt*c0.x; acc[1]+=wt*c0.y; acc[2]+=wt*c1.x; acc[3]+=wt*c1.y;
        acc[4]+=wt*c2.x; acc[5]+=wt*c2.y; acc[6]+=wt*c3.x; acc[7]+=wt*c3.y;
    }
    float4* o = (float4*)&g_bufA[node * 128 + l16 * 8];
    o[0] = make_float4(acc[0]*dd, acc[1]*dd, acc[2]*dd, acc[3]*dd);
    o[1] = make_float4(acc[4]*dd, acc[5]*dd, acc[6]*dd, acc[7]*dd);
}

// ---------------- 2-pass MoE GEMM, M=64 tiles, 256 thr, 2 CTAs/SM ----------------
#define SMA_HI  0                          // 64 x 256B = 16KB
#define SMB_HI  16384                      // 32KB
#define SMB_LO  49152                      // 32KB
#define SM_BIAS 81920                      // 384 floats
#define SM_GATE (81920 + 1536)             // 192 floats
#define SM_BAT  (81920 + 2304)             // 64 ints
#define SMEM_MM (81920 + 2304 + 256)
#define SM_STG  SMB_HI                     // pool staging: 64*132*4 = 33792 <= 64KB B stage

#define AOFF(row, k) ((row) * 256 + (((((k) >> 3) ^ ((row) & 7))) << 4) + (((k) & 7) << 1))

__device__ __forceinline__ void mma_bf16(float* c, const uint32_t* a, const uint32_t* b) {
    asm volatile("mma.sync.aligned.m16n8k16.row.col.f32.bf16.bf16.f32 "
        "{%0,%1,%2,%3}, {%4,%5,%6,%7}, {%8,%9}, {%0,%1,%2,%3};"
        : "+f"(c[0]), "+f"(c[1]), "+f"(c[2]), "+f"(c[3])
        : "r"(a[0]), "r"(a[1]), "r"(a[2]), "r"(a[3]), "r"(b[0]), "r"(b[1]));
}

__device__ __forceinline__ void cp16(uint32_t dst, const void* src) {
    asm volatile("cp.async.cg.shared.global [%0], [%1], 16;" :: "r"(dst), "l"(src));
}

// B tile (hi+lo) into the single stage: 2048+2048 chunks, 256 threads x 8 iters
__device__ __forceinline__ void issueB(uint32_t smb, int layer, int e, int tid) {
    const uint4* bh = (const uint4*)(g_Wh + (layer * 3 + e) * 16384);
    const uint4* bl = (const uint4*)(g_Wl + (layer * 3 + e) * 16384);
    #pragma unroll
    for (int it = 0; it < 8; it++) {
        int idx = it * 256 + tid;          // 0..2047
        int n = idx >> 4, kc = idx & 15;
        int off = n * 256 + ((kc ^ (n & 7)) << 4);
        cp16(smb + SMB_HI + off, bh + idx);
        cp16(smb + SMB_LO + off, bl + idx);
    }
    asm volatile("cp.async.commit_group;");
}

__global__ void __launch_bounds__(256, 2) k_gemm_mma(const float* __restrict__ bias3,
                                                     const int* __restrict__ batch,
                                                     int layer) {
    extern __shared__ __align__(16) char smc[];
    const uint32_t smb = smem_u32(smc);
    const int tid = threadIdx.x;
    const int baseM = blockIdx.x * 64;
    const float* gate = layer ? g_gate1 : g_gate0;
    float* bias_s = (float*)(smc + SM_BIAS);
    float* gate_s = (float*)(smc + SM_GATE);
    int*   bat_s  = (int*)(smc + SM_BAT);

    issueB(smb, layer, 0, tid);

    if (tid < 192) {
        int gi = baseM * 3 + tid;
        gate_s[tid] = (gi < Nn * 3) ? gate[gi] : 0.f;
    }
    for (int i = tid; i < 384; i += 256) bias_s[i] = bias3[i];
    if (layer && tid < 64) {
        int nn = baseM + tid;
        bat_s[tid] = (nn < Nn) ? batch[nn] : -1;
    }

    // ---- build A tile (bf16 hi only, swizzled): 1024 chunks ----
    #pragma unroll
    for (int it = 0; it < 4; it++) {
        int idx = it * 256 + tid;          // 0..1023
        int row = idx >> 4, kc = idx & 15;
        int grow = baseM + row;
        float4 v0 = make_float4(0.f,0.f,0.f,0.f), v1 = v0;
        if (grow < Nn) {
            const float4* p = (const float4*)(g_bufA + grow * 128 + kc * 8);
            v0 = p[0]; v1 = p[1];
        }
        float f[8] = {v0.x, v0.y, v0.z, v0.w, v1.x, v1.y, v1.z, v1.w};
        __nv_bfloat16 h[8];
        #pragma unroll
        for (int j = 0; j < 8; j++) h[j] = __float2bfloat16_rn(f[j]);
        int off = row * 256 + ((kc ^ (row & 7)) << 4);
        *(uint4*)(smc + SMA_HI + off) = *(uint4*)h;
    }

    const int lane = tid & 31, wid = tid >> 5;
    const int warpM = wid >> 2, warpN = wid & 3;   // 2x4 warps, each m32 x n32
    const int g = lane >> 2, t4 = lane & 3;

    float out[2][4][4];
    #pragma unroll
    for (int mt = 0; mt < 2; mt++)
        #pragma unroll
        for (int nt = 0; nt < 4; nt++)
            #pragma unroll
            for (int j = 0; j < 4; j++) out[mt][nt][j] = 0.f;

    #pragma unroll 1
    for (int e = 0; e < 3; e++) {
        asm volatile("cp.async.wait_group 0;");
        __syncthreads();   // B(e) + A (e=0) visible

        float acc[2][4][4];
        #pragma unroll
        for (int mt = 0; mt < 2; mt++)
            #pragma unroll
            for (int nt = 0; nt < 4; nt++)
                #pragma unroll
                for (int j = 0; j < 4; j++) acc[mt][nt][j] = 0.f;

        #pragma unroll
        for (int ks = 0; ks < 8; ks++) {
            const int c0 = ks * 16 + t4 * 2;
            uint32_t afh[2][4], bfh[4][2], bfl[4][2];
            #pragma unroll
            for (int mt = 0; mt < 2; mt++) {
                int r0 = warpM * 32 + mt * 16 + g;
                afh[mt][0] = *(const uint32_t*)(smc + SMA_HI + AOFF(r0,     c0));
                afh[mt][1] = *(const uint32_t*)(smc + SMA_HI + AOFF(r0 + 8, c0));
                afh[mt][2] = *(const uint32_t*)(smc + SMA_HI + AOFF(r0,     c0 + 8));
                afh[mt][3] = *(const uint32_t*)(smc + SMA_HI + AOFF(r0 + 8, c0 + 8));
            }
            #pragma unroll
            for (int nt = 0; nt < 4; nt++) {
                int n0 = warpN * 32 + nt * 8 + g;
                bfh[nt][0] = *(const uint32_t*)(smc + SMB_HI + AOFF(n0, c0));
                bfh[nt][1] = *(const uint32_t*)(smc + SMB_HI + AOFF(n0, c0 + 8));
                bfl[nt][0] = *(const uint32_t*)(smc + SMB_LO + AOFF(n0, c0));
                bfl[nt][1] = *(const uint32_t*)(smc + SMB_LO + AOFF(n0, c0 + 8));
            }
            #pragma unroll
            for (int mt = 0; mt < 2; mt++)
                #pragma unroll
                for (int nt = 0; nt < 4; nt++) {
                    mma_bf16(acc[mt][nt], afh[mt], bfh[nt]);
                    mma_bf16(acc[mt][nt], afh[mt], bfl[nt]);
                }
        }

        // ---- gated relu epilogue ----
        #pragma unroll
        for (int mt = 0; mt < 2; mt++) {
            int rloc = warpM * 32 + mt * 16 + g;
            float g0 = gate_s[rloc * 3 + e];
            float g1 = gate_s[(rloc + 8) * 3 + e];
            #pragma unroll
            for (int nt = 0; nt < 4; nt++) {
                int col = warpN * 32 + nt * 8 + t4 * 2;
                float bb0 = bias_s[e * 128 + col], bb1 = bias_s[e * 128 + col + 1];
                out[mt][nt][0] += g0 * fmaxf(acc[mt][nt][0] + bb0, 0.f);
                out[mt][nt][1] += g0 * fmaxf(acc[mt][nt][1] + bb1, 0.f);
                out[mt][nt][2] += g1 * fmaxf(acc[mt][nt][2] + bb0, 0.f);
                out[mt][nt][3] += g1 * fmaxf(acc[mt][nt][3] + bb1, 0.f);
            }
        }

        if (e < 2) {
            __syncthreads();               // all warps done reading B(e)
            issueB(smb, layer, e + 1, tid);
        }
    }

    if (!layer) {
        // ---- layer 0: write h as bf16 for the next gather ----
        #pragma unroll
        for (int mt = 0; mt < 2; mt++) {
            int r0 = baseM + warpM * 32 + mt * 16 + g;
            #pragma unroll
            for (int nt = 0; nt < 4; nt++) {
                int col = warpN * 32 + nt * 8 + t4 * 2;
                __nv_bfloat16 p0[2] = {__float2bfloat16_rn(out[mt][nt][0]),
                                       __float2bfloat16_rn(out[mt][nt][1])};
                __nv_bfloat16 p1[2] = {__float2bfloat16_rn(out[mt][nt][2]),
                                       __float2bfloat16_rn(out[mt][nt][3])};
                if (r0 < Nn)     *(uint32_t*)&g_hbf[r0 * 128 + col]       = *(uint32_t*)p0;
                if (r0 + 8 < Nn) *(uint32_t*)&g_hbf[(r0 + 8) * 128 + col] = *(uint32_t*)p1;
            }
        }
    } else {
        // ---- layer 1: fused pooling via smem staging + segment scan ----
        __syncthreads();
        float* stg = (float*)(smc + SM_STG);
        #pragma unroll
        for (int mt = 0; mt < 2; mt++) {
            int rloc = warpM * 32 + mt * 16 + g;
            #pragma unroll
            for (int nt = 0; nt < 4; nt++) {
                int col = warpN * 32 + nt * 8 + t4 * 2;
                stg[rloc * 132 + col]           = out[mt][nt][0];
                stg[rloc * 132 + col + 1]       = out[mt][nt][1];
                stg[(rloc + 8) * 132 + col]     = out[mt][nt][2];
                stg[(rloc + 8) * 132 + col + 1] = out[mt][nt][3];
            }
        }
        __syncthreads();
        int col = tid & 127, grp = tid >> 7;   // 2 groups x 32 rows
        int rbeg = grp * 32;
        int cur = -2; float acc = 0.f; float cnt = 0.f;
        #pragma unroll 4
        for (int r = rbeg; r < rbeg + 32; r++) {
            int b = bat_s[r];
            if (b != cur) {
                if (cur >= 0) {
                    atomicAdd(&g_sums[cur * 128 + col], acc);
                    if (col == 0) atomicAdd(&g_cnt[cur], cnt);
                }
                cur = b; acc = 0.f; cnt = 0.f;
            }
            if (b >= 0) { acc += stg[r * 132 + col]; cnt += 1.f; }
        }
        if (cur >= 0) {
            atomicAdd(&g_sums[cur * 128 + col], acc);
            if (col == 0) atomicAdd(&g_cnt[cur], cnt);
        }
    }
}

// ---------------- final linear + scratch cleanup ----------------
__global__ void __launch_bounds__(256) k_final(const float* __restrict__ Wf,
                                               const float* __restrict__ bf,
                                               float* __restrict__ out) {
    int t = threadIdx.x;
    if (blockIdx.x >= NG) {
        int idx = (blockIdx.x - NG) * 256 + t;
        if (idx < Nn) g_deg[idx] = 0;
        if (idx < 128) g_scanFlag[idx] = 0;
        return;
    }
    __shared__ float p[128];
    int g = blockIdx.x;
    float inv = 1.0f / fmaxf(g_cnt[g], 1.0f);
    if (t < 128) { p[t] = g_sums[g * 128 + t] * inv; g_sums[g * 128 + t] = 0.f; }
    __syncthreads();
    if (t == 0) g_cnt[g] = 0.f;
    if (t < OUTC) {
        float acc = bf[t];
        #pragma unroll 16
        for (int k = 0; k < 128; k++)
            acc += p[k] * Wf[k * OUTC + t];
        out[g * OUTC + t] = acc;
    }
}

// ---------------- launch ----------------
extern "C" void kernel_launch(void* const* d_in, const int* in_sizes, int n_in,
                              void* d_out, int out_size) {
    const float* x     = (const float*)d_in[0];
    const float* top   = (const float*)d_in[1];
    const int*   ei    = (const int*)d_in[2];
    const int*   batch = (const int*)d_in[3];
    const float* W0    = (const float*)d_in[4];
    const float* b0    = (const float*)d_in[5];
    const float* Wg0   = (const float*)d_in[6];
    const float* W1    = (const float*)d_in[7];
    const float* b1    = (const float*)d_in[8];
    const float* Wg1   = (const float*)d_in[9];
    const float* Wf    = (const float*)d_in[10];
    const float* bf    = (const float*)d_in[11];
    float*       out   = (float*)d_out;

    cudaFuncSetAttribute(k_gemm_mma, cudaFuncAttributeMaxDynamicSharedMemorySize, SMEM_MM);

    const __nv_bfloat16* xbf; const __nv_bfloat16* hbf;
    cudaGetSymbolAddress((void**)&xbf, g_xbf);
    cudaGetSymbolAddress((void**)&hbf, g_hbf);

    const int gemmGrid = (Nn + 63) / 64;   // 782

    k_init<<<(Nn * 32 + 255) / 256, 256>>>(x, W0, W1, top, Wg0, Wg1, ei);   // 0
    k_scan<<<98, 512>>>();                                                  // 1
    k_fill<<<(Ee + 255) / 256, 256>>>(ei);                                  // 2
    k_agg<<<3125, 256>>>(xbf);                                              // 3
    k_gemm_mma<<<gemmGrid, 256, SMEM_MM>>>(b0, batch, 0);                   // 4
    k_agg<<<3125, 256>>>(hbf);                                              // 5
    k_gemm_mma<<<gemmGrid, 256, SMEM_MM>>>(b1, batch, 1);                   // 6
    k_final<<<NG + 196, 256>>>(Wf, bf, out);                                // 7
}